// round 12
// baseline (speedup 1.0000x reference)
#include <cuda_runtime.h>
#include <cuda_bf16.h>
#include <cstdint>

#define Bn 128
#define Sn 256
#define Hn 1024
#define Tn 20
#define G4n 4096
#define DTn 1044
#define START_I 19
#define NBLK 128u

typedef unsigned long long u64t;

// ---------------- device scratch ----------------
__device__ float g_G[(size_t)Sn * Bn * G4n];                 // x-projection + biases (fp32)
__device__ float g_h[2][Bn * Hn];                            // fp32 h (for logits)
__device__ float g_Wtag[Tn * G4n];                           // one-hot columns of W_ih
__device__ __align__(16) unsigned char g_hA8h[2][131072];    // h int8-hi A-frags (m16k32 layout)
__device__ __align__(16) unsigned char g_hA8l[2][131072];    // h int8-lo A-frags
__device__ __align__(16) uint2 g_WB8h[524288];               // Whh int8-hi B-frags (4MB)
__device__ __align__(16) uint2 g_WB8l[524288];               // Whh int8-lo B-frags (4MB)
__device__ __align__(16) uint4 g_xh[4194304];                // x bf16-hi A-frags (67MB, xproj)
__device__ __align__(16) uint4 g_xl[4194304];                // x bf16-lo A-frags (67MB)
__device__ __align__(16) uint2 g_wfh[1048576];               // W_ih bf16-hi B-frags (8MB)
__device__ __align__(16) uint2 g_wfl[1048576];               // W_ih bf16-lo B-frags (8MB)
__device__ int   g_ptag[Bn];
__device__ double g_loss;
__device__ unsigned g_bar_arrive, g_bar_phase, g_ptag_ready;

// ---------------- mma wrappers ----------------
__device__ __forceinline__ void mma_bf16(float* d,
    uint32_t a0, uint32_t a1, uint32_t a2, uint32_t a3,
    uint32_t b0, uint32_t b1)
{
    asm volatile(
        "mma.sync.aligned.m16n8k16.row.col.f32.bf16.bf16.f32 "
        "{%0,%1,%2,%3}, {%4,%5,%6,%7}, {%8,%9}, {%0,%1,%2,%3};"
        : "+f"(d[0]), "+f"(d[1]), "+f"(d[2]), "+f"(d[3])
        : "r"(a0), "r"(a1), "r"(a2), "r"(a3), "r"(b0), "r"(b1));
}
__device__ __forceinline__ void imma(int* d,
    uint32_t a0, uint32_t a1, uint32_t a2, uint32_t a3,
    uint32_t b0, uint32_t b1)
{
    asm volatile(
        "mma.sync.aligned.m16n8k32.row.col.s32.s8.s8.s32 "
        "{%0,%1,%2,%3}, {%4,%5,%6,%7}, {%8,%9}, {%0,%1,%2,%3};"
        : "+r"(d[0]), "+r"(d[1]), "+r"(d[2]), "+r"(d[3])
        : "r"(a0), "r"(a1), "r"(a2), "r"(a3), "r"(b0), "r"(b1));
}
__device__ __forceinline__ uint32_t pack_bf16_hi(float x, float y) {
    __nv_bfloat16 bx = __float2bfloat16(x), by = __float2bfloat16(y);
    return (uint32_t)__bfloat16_as_ushort(bx) | ((uint32_t)__bfloat16_as_ushort(by) << 16);
}
__device__ __forceinline__ uint32_t pack_bf16_lo(float x, float y) {
    __nv_bfloat16 bx = __float2bfloat16(x), by = __float2bfloat16(y);
    float rx = x - __bfloat162float(bx), ry = y - __bfloat162float(by);
    __nv_bfloat16 lx = __float2bfloat16(rx), ly = __float2bfloat16(ry);
    return (uint32_t)__bfloat16_as_ushort(lx) | ((uint32_t)__bfloat16_as_ushort(ly) << 16);
}

// ---------------- software grid barrier ----------------
__device__ __forceinline__ void grid_bar() {
    __syncthreads();
    if (threadIdx.x == 0) {
        unsigned gen = *(volatile unsigned*)&g_bar_phase;
        __threadfence();
        unsigned t = atomicAdd(&g_bar_arrive, 1u);
        if (t == NBLK - 1u) {
            *(volatile unsigned*)&g_bar_arrive = 0u;
            __threadfence();
            *(volatile unsigned*)&g_bar_phase = gen + 1u;
        } else {
            while (*(volatile unsigned*)&g_bar_phase == gen) {}
            __threadfence();
        }
    }
    __syncthreads();
}

// ---------------- init: misc + Whh int8 B-frags + W_ih bf16 B-frags ----------------
__global__ void init_kernel(const float* __restrict__ Wih, const float* __restrict__ Whh) {
    int idx = blockIdx.x * blockDim.x + threadIdx.x;   // 0 .. 4194303
    if (idx < Bn) g_ptag[idx] = START_I;
    if (idx == 0) { g_loss = 0.0; g_bar_arrive = 0u; g_ptag_ready = 0u; }
    if (idx < Tn * G4n) {
        int t = idx >> 12;
        int n = idx & (G4n - 1);
        g_Wtag[idx] = Wih[(size_t)n * DTn + Hn + t];
    }
    if (idx < 524288) {   // Whh int8 B-frags: idx = ((bid*4+nt)*32+kt)*32+lane
        int lane = idx & 31;
        int kt   = (idx >> 5) & 31;
        int nt   = (idx >> 10) & 3;
        int bid  = idx >> 12;
        int g = lane >> 2, t = lane & 3;
        int n = nt * 1024 + bid * 8 + g;
        const float* W = Whh + (size_t)n * Hn + kt * 32;
        uint32_t bh0 = 0, bh1 = 0, bl0 = 0, bl1 = 0;
#pragma unroll
        for (int i = 0; i < 4; i++) {
            int w19a = __float2int_rn(W[4 * t + i] * 524288.f);
            int w19b = __float2int_rn(W[16 + 4 * t + i] * 524288.f);
            int whA = (w19a + 128) >> 8, wlA = w19a - (whA << 8);
            int whB = (w19b + 128) >> 8, wlB = w19b - (whB << 8);
            bh0 |= (uint32_t)(whA & 0xFF) << (8 * i);
            bl0 |= (uint32_t)(wlA & 0xFF) << (8 * i);
            bh1 |= (uint32_t)(whB & 0xFF) << (8 * i);
            bl1 |= (uint32_t)(wlB & 0xFF) << (8 * i);
        }
        g_WB8h[idx] = make_uint2(bh0, bh1);
        g_WB8l[idx] = make_uint2(bl0, bl1);
    }
    if (idx < 1048576) {   // W_ih bf16 B-frags (xproj)
        int lane = idx & 31;
        int kt   = (idx >> 5) & 63;
        int nt2  = idx >> 11;
        int g = lane >> 2, tig = lane & 3;
        int n = nt2 * 8 + g;
        int k0 = kt * 16 + 2 * tig;
        const float* W = Wih + (size_t)n * DTn;
        float a = W[k0], b = W[k0 + 1], c = W[k0 + 8], d = W[k0 + 9];
        g_wfh[idx] = make_uint2(pack_bf16_hi(a, b), pack_bf16_hi(c, d));
        g_wfl[idx] = make_uint2(pack_bf16_lo(a, b), pack_bf16_lo(c, d));
    }
}

// ---------------- x -> A-fragment hi/lo bf16 (one-time, xproj) ----------------
__global__ void xprep_kernel(const float* __restrict__ x) {
    int idx = blockIdx.x * blockDim.x + threadIdx.x;
    int lane = idx & 31;
    int kt = (idx >> 5) & 63;
    int mt = idx >> 11;
    int g = lane >> 2, tig = lane & 3;
    int m0 = mt * 16 + g;
    int m1 = m0 + 8;
    int k0 = kt * 16 + 2 * tig;
    const float* r0 = x + ((size_t)((m0 & 127) * 256 + (m0 >> 7))) * Hn;
    const float* r1 = x + ((size_t)((m1 & 127) * 256 + (m1 >> 7))) * Hn;
    float2 v00 = *(const float2*)(r0 + k0);
    float2 v01 = *(const float2*)(r0 + k0 + 8);
    float2 v10 = *(const float2*)(r1 + k0);
    float2 v11 = *(const float2*)(r1 + k0 + 8);
    g_xh[idx] = make_uint4(pack_bf16_hi(v00.x, v00.y), pack_bf16_hi(v10.x, v10.y),
                           pack_bf16_hi(v01.x, v01.y), pack_bf16_hi(v11.x, v11.y));
    g_xl[idx] = make_uint4(pack_bf16_lo(v00.x, v00.y), pack_bf16_lo(v10.x, v10.y),
                           pack_bf16_lo(v01.x, v01.y), pack_bf16_lo(v11.x, v11.y));
}

__global__ void dummy_kernel() {}

// ---------------- phase 1: x-projection via HMMA bf16 3-split (R10, unchanged) ----------------
__global__ __launch_bounds__(256) void xproj_kernel(
    const float* __restrict__ bih, const float* __restrict__ bhh)
{
    const int tid = threadIdx.x;
    const int wid = tid >> 5, lane = tid & 31;
    const int g = lane >> 2, tig = lane & 3;
    const int wm = wid & 1, wn = wid >> 1;
    const int mt0 = blockIdx.y * 8 + wm * 4;
    const int nt0 = blockIdx.x * 16 + wn * 4;

    const uint4* Ah = g_xh + (size_t)mt0 * 2048 + lane;
    const uint4* Al = g_xl + (size_t)mt0 * 2048 + lane;
    const uint2* Bh = g_wfh + (size_t)nt0 * 2048 + lane;
    const uint2* Bl = g_wfl + (size_t)nt0 * 2048 + lane;

    float dacc[4][4][4];
#pragma unroll
    for (int i = 0; i < 4; i++)
#pragma unroll
        for (int j = 0; j < 4; j++)
#pragma unroll
            for (int e = 0; e < 4; e++) dacc[i][j][e] = 0.f;

    uint4 ah[4], al[4]; uint2 bh[4], bl[4];
#pragma unroll
    for (int i = 0; i < 4; i++) { ah[i] = __ldg(Ah + i * 2048); al[i] = __ldg(Al + i * 2048); }
#pragma unroll
    for (int j = 0; j < 4; j++) { bh[j] = __ldg(Bh + j * 2048); bl[j] = __ldg(Bl + j * 2048); }

    for (int kt = 0; kt < 64; kt++) {
        uint4 ahn[4], aln[4]; uint2 bhn[4], bln[4];
        if (kt < 63) {
#pragma unroll
            for (int i = 0; i < 4; i++) {
                ahn[i] = __ldg(Ah + i * 2048 + (kt + 1) * 32);
                aln[i] = __ldg(Al + i * 2048 + (kt + 1) * 32);
            }
#pragma unroll
            for (int j = 0; j < 4; j++) {
                bhn[j] = __ldg(Bh + j * 2048 + (kt + 1) * 32);
                bln[j] = __ldg(Bl + j * 2048 + (kt + 1) * 32);
            }
        }
#pragma unroll
        for (int i = 0; i < 4; i++)
#pragma unroll
            for (int j = 0; j < 4; j++)
                mma_bf16(dacc[i][j], ah[i].x, ah[i].y, ah[i].z, ah[i].w, bh[j].x, bh[j].y);
#pragma unroll
        for (int i = 0; i < 4; i++)
#pragma unroll
            for (int j = 0; j < 4; j++)
                mma_bf16(dacc[i][j], al[i].x, al[i].y, al[i].z, al[i].w, bh[j].x, bh[j].y);
#pragma unroll
        for (int i = 0; i < 4; i++)
#pragma unroll
            for (int j = 0; j < 4; j++)
                mma_bf16(dacc[i][j], ah[i].x, ah[i].y, ah[i].z, ah[i].w, bl[j].x, bl[j].y);
#pragma unroll
        for (int i = 0; i < 4; i++) { ah[i] = ahn[i]; al[i] = aln[i]; }
#pragma unroll
        for (int j = 0; j < 4; j++) { bh[j] = bhn[j]; bl[j] = bln[j]; }
    }

#pragma unroll
    for (int j = 0; j < 4; j++) {
        int n = (nt0 + j) * 8 + 2 * tig;
        float b0 = bih[n] + bhh[n];
        float b1 = bih[n + 1] + bhh[n + 1];
#pragma unroll
        for (int i = 0; i < 4; i++) {
            int m = (mt0 + i) * 16 + g;
            *(float2*)(g_G + (size_t)m * G4n + n) =
                make_float2(dacc[i][j][0] + b0, dacc[i][j][1] + b1);
            *(float2*)(g_G + (size_t)(m + 8) * G4n + n) =
                make_float2(dacc[i][j][2] + b0, dacc[i][j][3] + b1);
        }
    }
}

// ---------------- persistent loop: s8 IMMA fixed-point recurrent GEMM ----------------
// smem: [0..1024) red, [1024..33792) WB8h, [33792..66560) WB8l
#define LOOP_SMEM 66560

__global__ __launch_bounds__(256, 1) void loop_kernel(
    const float* __restrict__ Wout, const float* __restrict__ bout,
    const int* __restrict__ tags, const int* __restrict__ mask,
    float* __restrict__ out)
{
    extern __shared__ __align__(16) unsigned char smem[];
    float* red = (float*)smem;
    const uint2* BH = (const uint2*)(smem + 1024);
    const uint2* BL = (const uint2*)(smem + 33792);

    const int bid = blockIdx.x;
    const int tid = threadIdx.x;
    const int wm = tid >> 5;
    const int lane = tid & 31;
    const int g = lane >> 2, tig = lane & 3;

    // resident Whh int8 B-frags (64KB one-time copy)
    {
        const uint2* srcH = g_WB8h + (size_t)bid * 4096;
        const uint2* srcL = g_WB8l + (size_t)bid * 4096;
        uint2* dstH = (uint2*)(smem + 1024);
        uint2* dstL = (uint2*)(smem + 33792);
        for (int u = tid; u < 4096; u += 256) { dstH[u] = srcH[u]; dstL[u] = srcL[u]; }
    }
    __syncthreads();

    const int b1 = wm * 16 + g;
    const int b2 = b1 + 8;
    const int kkg0 = bid * 8 + 2 * tig;

    // epilogue A-frag store offsets (byte addresses into g_hA8*)
    const int ku = ((bid & 3) << 3) + 2 * tig;
    const int ktA = bid >> 2;
    const int half = ku >> 4, kq = (ku >> 2) & 3, kb = ku & 3;
    const int lanep = g * 4 + kq;
    const int offA = (((b1 >> 4) * 32 + ktA) * 32 + lanep) * 16 + (half * 2 + ((b1 >> 3) & 1)) * 4 + kb;
    const int offB = (((b2 >> 4) * 32 + ktA) * 32 + lanep) * 16 + (half * 2 + ((b2 >> 3) & 1)) * 4 + kb;

    const float invS = 1.0f / (32512.0f * 524288.0f);

    float creg[2][2] = {{0.f, 0.f}, {0.f, 0.f}};
    double lossAcc = 0.0;

    for (int s = 0; s < Sn; s++) {
        // prefetch G (independent of GEMM/ptag)
        float2 Gv[2][4];
#pragma unroll
        for (int r2 = 0; r2 < 2; r2++) {
            int r = r2 ? b2 : b1;
            const float* Gp = g_G + (size_t)(s * Bn + r) * G4n + kkg0;
#pragma unroll
            for (int nt = 0; nt < 4; nt++)
                Gv[r2][nt] = __ldcs((const float2*)(Gp + nt * 1024));
        }

        int acch[4][4], accm[4][4];
#pragma unroll
        for (int nt = 0; nt < 4; nt++)
#pragma unroll
            for (int e = 0; e < 4; e++) { acch[nt][e] = 0; accm[nt][e] = 0; }

        if (s > 0) {
            const int par = s & 1;
            const uint4* Ah4 = (const uint4*)g_hA8h[par] + (wm * 1024 + lane);
            const uint4* Al4 = (const uint4*)g_hA8l[par] + (wm * 1024 + lane);
            uint4 ahs[3], als[3];
#pragma unroll
            for (int d = 0; d < 3; d++) {
                ahs[d] = __ldcg(Ah4 + d * 32);
                als[d] = __ldcg(Al4 + d * 32);
            }
#pragma unroll
            for (int kt = 0; kt < 32; kt++) {
                const int sl = kt % 3;
                uint4 ah = ahs[sl], al = als[sl];
                if (kt + 3 < 32) {
                    ahs[sl] = __ldcg(Ah4 + (kt + 3) * 32);
                    als[sl] = __ldcg(Al4 + (kt + 3) * 32);
                }
                uint2 bh0 = BH[(0 * 32 + kt) * 32 + lane];
                uint2 bh1 = BH[(1 * 32 + kt) * 32 + lane];
                uint2 bh2 = BH[(2 * 32 + kt) * 32 + lane];
                uint2 bh3 = BH[(3 * 32 + kt) * 32 + lane];
                imma(acch[0], ah.x, ah.y, ah.z, ah.w, bh0.x, bh0.y);
                imma(acch[1], ah.x, ah.y, ah.z, ah.w, bh1.x, bh1.y);
                imma(acch[2], ah.x, ah.y, ah.z, ah.w, bh2.x, bh2.y);
                imma(acch[3], ah.x, ah.y, ah.z, ah.w, bh3.x, bh3.y);
                uint2 bl0 = BL[(0 * 32 + kt) * 32 + lane];
                uint2 bl1 = BL[(1 * 32 + kt) * 32 + lane];
                uint2 bl2 = BL[(2 * 32 + kt) * 32 + lane];
                uint2 bl3 = BL[(3 * 32 + kt) * 32 + lane];
                imma(accm[0], ah.x, ah.y, ah.z, ah.w, bl0.x, bl0.y);
                imma(accm[1], ah.x, ah.y, ah.z, ah.w, bl1.x, bl1.y);
                imma(accm[2], ah.x, ah.y, ah.z, ah.w, bl2.x, bl2.y);
                imma(accm[3], ah.x, ah.y, ah.z, ah.w, bl3.x, bl3.y);
                imma(accm[0], al.x, al.y, al.z, al.w, bh0.x, bh0.y);
                imma(accm[1], al.x, al.y, al.z, al.w, bh1.x, bh1.y);
                imma(accm[2], al.x, al.y, al.z, al.w, bh2.x, bh2.y);
                imma(accm[3], al.x, al.y, al.z, al.w, bh3.x, bh3.y);
            }
        }

        // wait for previous step's logits (ptag) — normally zero-wait
        if (s > 0) {
            if (tid == 0) {
                while (*(volatile unsigned*)&g_ptag_ready < (unsigned)s * 128u) {}
            }
            __syncthreads();
        }

        // ---- epilogue ----
        const int po = (s & 1) ^ 1;
        {
            int pt1 = __ldcg(&g_ptag[b1]);
            int pt2 = __ldcg(&g_ptag[b2]);
            const float* W1 = g_Wtag + pt1 * G4n + kkg0;
            const float* W2 = g_Wtag + pt2 * G4n + kkg0;
#pragma unroll
            for (int r2 = 0; r2 < 2; r2++) {
                int r = r2 ? b2 : b1;
                const float* Wt = r2 ? W2 : W1;
                float h01[2];
#pragma unroll
                for (int e = 0; e < 2; e++) {
                    int de = r2 * 2 + e;
                    float G0 = e ? Gv[r2][0].y : Gv[r2][0].x;
                    float G1 = e ? Gv[r2][1].y : Gv[r2][1].x;
                    float G2 = e ? Gv[r2][2].y : Gv[r2][2].x;
                    float G3 = e ? Gv[r2][3].y : Gv[r2][3].x;
                    float gi = ((float)acch[0][de] * 65536.f + (float)accm[0][de] * 256.f) * invS + G0 + Wt[e];
                    float gf = ((float)acch[1][de] * 65536.f + (float)accm[1][de] * 256.f) * invS + G1 + Wt[1024 + e];
                    float gg = ((float)acch[2][de] * 65536.f + (float)accm[2][de] * 256.f) * invS + G2 + Wt[2048 + e];
                    float go = ((float)acch[3][de] * 65536.f + (float)accm[3][de] * 256.f) * invS + G3 + Wt[3072 + e];
                    gi = 1.f / (1.f + __expf(-gi));
                    gf = 1.f / (1.f + __expf(-gf));
                    gg = tanhf(gg);
                    go = 1.f / (1.f + __expf(-go));
                    creg[r2][e] = gf * creg[r2][e] + gi * gg;
                    h01[e] = go * tanhf(creg[r2][e]);
                }
                *(float2*)(g_h[po] + r * Hn + kkg0) = make_float2(h01[0], h01[1]);
                // int8 fixed-point A-frag stores
                int h16a = __float2int_rn(h01[0] * 32512.f);
                int h16b = __float2int_rn(h01[1] * 32512.f);
                int ahiA = (h16a + 128) >> 8, aloA = h16a - (ahiA << 8);
                int ahiB = (h16b + 128) >> 8, aloB = h16b - (ahiB << 8);
                unsigned short sh = (unsigned short)((ahiA & 0xFF) | ((ahiB & 0xFF) << 8));
                unsigned short slv = (unsigned short)((aloA & 0xFF) | ((aloB & 0xFF) << 8));
                int off = r2 ? offB : offA;
                *(unsigned short*)(g_hA8h[po] + off) = sh;
                *(unsigned short*)(g_hA8l[po] + off) = slv;
            }
        }
        grid_bar();

        // ---- logits for batch = bid (serial, R8-proven) ----
        {
            const float4* h4 = (const float4*)(g_h[po] + bid * Hn);
            float4 hvv = __ldcg(h4 + tid);
            const float4* W4 = (const float4*)Wout;
            float p[Tn];
#pragma unroll
            for (int t = 0; t < Tn; t++) {
                float4 w = __ldg(W4 + t * 256 + tid);
                p[t] = hvv.x * w.x + hvv.y * w.y + hvv.z * w.z + hvv.w * w.w;
            }
#pragma unroll
            for (int t = 0; t < Tn; t++) {
#pragma unroll
                for (int o = 16; o > 0; o >>= 1)
                    p[t] += __shfl_xor_sync(0xffffffffu, p[t], o);
            }
            if ((tid & 31) == 0) {
#pragma unroll
                for (int t = 0; t < Tn; t++) red[(tid >> 5) * Tn + t] = p[t];
            }
            __syncthreads();
            if (tid < 32) {
                float l = -3.402823466e38f;
                if (tid < Tn) {
                    l = bout[tid];
#pragma unroll
                    for (int w = 0; w < 8; w++) l += red[w * Tn + tid];
                }
                float v = l; int idx = tid;
#pragma unroll
                for (int o = 16; o > 0; o >>= 1) {
                    float v2 = __shfl_xor_sync(0xffffffffu, v, o);
                    int   i2 = __shfl_xor_sync(0xffffffffu, idx, o);
                    if (v2 > v || (v2 == v && i2 < idx)) { v = v2; idx = i2; }
                }
                if (tid == 0) g_ptag[bid] = idx;
                if (mask[bid * Sn + s] != 0) {
                    float e = (tid < Tn) ? expf(l - v) : 0.f;
#pragma unroll
                    for (int o = 16; o > 0; o >>= 1)
                        e += __shfl_xor_sync(0xffffffffu, e, o);
                    int y = tags[bid * Sn + s];
                    float ly = __shfl_sync(0xffffffffu, l, y);
                    if (tid == 0) lossAcc += (double)(v + logf(e) - ly);
                }
                if (tid == 0) {
                    __threadfence();
                    atomicAdd(&g_ptag_ready, 1u);
                }
            }
            __syncthreads();
        }
    }

    if (tid == 0) atomicAdd(&g_loss, lossAcc);
    grid_bar();
    if (bid == 0 && tid == 0) out[0] = (float)(*(volatile double*)&g_loss);
}

// ---------------- launch ----------------
extern "C" void kernel_launch(void* const* d_in, const int* in_sizes, int n_in,
                              void* d_out, int out_size)
{
    const float *x = nullptr, *Wih = nullptr, *Whh = nullptr;
    const float *bih = nullptr, *bhh = nullptr, *Wout = nullptr, *bout = nullptr;
    const int *tags = nullptr, *maskp = nullptr;
    for (int i = 0; i < n_in; i++) {
        int sz = in_sizes[i];
        const void* p = d_in[i];
        switch (sz) {
            case 33554432: x = (const float*)p; break;
            case 4276224:  Wih = (const float*)p; break;
            case 4194304:  Whh = (const float*)p; break;
            case 4096:     if (!bih) bih = (const float*)p; else bhh = (const float*)p; break;
            case 32768:    if (!tags) tags = (const int*)p; else maskp = (const int*)p; break;
            case 20480:    Wout = (const float*)p; break;
            case 20:       bout = (const float*)p; break;
            default: break;
        }
    }

    cudaFuncSetAttribute(loop_kernel, cudaFuncAttributeMaxDynamicSharedMemorySize, LOOP_SMEM);

    init_kernel<<<16384, 256>>>(Wih, Whh);                               // #1
    xprep_kernel<<<16384, 256>>>(x);                                     // #2
    xproj_kernel<<<dim3(32, 256), 256>>>(bih, bhh);                      // #3
    loop_kernel<<<NBLK, 256, LOOP_SMEM>>>(Wout, bout, tags, maskp, (float*)d_out);  // #4 (profiled)
}

// round 13
// speedup vs baseline: 1.0708x; 1.0708x over previous
#include <cuda_runtime.h>
#include <cuda_bf16.h>
#include <cstdint>

#define Bn 128
#define Sn 256
#define Hn 1024
#define Tn 20
#define G4n 4096
#define DTn 1044
#define START_I 19
#define NBLK 128u

typedef unsigned long long u64t;

// ---------------- device scratch ----------------
__device__ float g_G[(size_t)Sn * Bn * G4n];                 // x-projection + biases (fp32)
__device__ float g_h[2][Bn * Hn];                            // fp32 h (for logits)
__device__ float g_Wtag[Tn * G4n];                           // one-hot columns of W_ih
__device__ __align__(16) unsigned char g_hA8h[2][131072];    // h int8-hi A-frags (m16k32 layout)
__device__ __align__(16) unsigned char g_hA8l[2][131072];    // h int8-lo A-frags
__device__ __align__(16) uint2 g_WB8h[524288];               // Whh int8-hi B-frags (4MB)
__device__ __align__(16) uint2 g_WB8l[524288];               // Whh int8-lo B-frags (4MB)
__device__ __align__(16) uint4 g_xh[4194304];                // x bf16-hi A-frags (67MB, xproj)
__device__ __align__(16) uint4 g_xl[4194304];                // x bf16-lo A-frags (67MB)
__device__ __align__(16) uint2 g_wfh[1048576];               // W_ih bf16-hi B-frags (8MB)
__device__ __align__(16) uint2 g_wfl[1048576];               // W_ih bf16-lo B-frags (8MB)
__device__ int   g_ptag[Bn];
__device__ double g_loss;
__device__ unsigned g_bar_arrive, g_bar_phase, g_ptag_ready;

// ---------------- mma wrappers ----------------
__device__ __forceinline__ void mma_bf16(float* d,
    uint32_t a0, uint32_t a1, uint32_t a2, uint32_t a3,
    uint32_t b0, uint32_t b1)
{
    asm volatile(
        "mma.sync.aligned.m16n8k16.row.col.f32.bf16.bf16.f32 "
        "{%0,%1,%2,%3}, {%4,%5,%6,%7}, {%8,%9}, {%0,%1,%2,%3};"
        : "+f"(d[0]), "+f"(d[1]), "+f"(d[2]), "+f"(d[3])
        : "r"(a0), "r"(a1), "r"(a2), "r"(a3), "r"(b0), "r"(b1));
}
__device__ __forceinline__ void imma(int* d,
    uint32_t a0, uint32_t a1, uint32_t a2, uint32_t a3,
    uint32_t b0, uint32_t b1)
{
    asm volatile(
        "mma.sync.aligned.m16n8k32.row.col.s32.s8.s8.s32 "
        "{%0,%1,%2,%3}, {%4,%5,%6,%7}, {%8,%9}, {%0,%1,%2,%3};"
        : "+r"(d[0]), "+r"(d[1]), "+r"(d[2]), "+r"(d[3])
        : "r"(a0), "r"(a1), "r"(a2), "r"(a3), "r"(b0), "r"(b1));
}
__device__ __forceinline__ uint32_t pack_bf16_hi(float x, float y) {
    __nv_bfloat16 bx = __float2bfloat16(x), by = __float2bfloat16(y);
    return (uint32_t)__bfloat16_as_ushort(bx) | ((uint32_t)__bfloat16_as_ushort(by) << 16);
}
__device__ __forceinline__ uint32_t pack_bf16_lo(float x, float y) {
    __nv_bfloat16 bx = __float2bfloat16(x), by = __float2bfloat16(y);
    float rx = x - __bfloat162float(bx), ry = y - __bfloat162float(by);
    __nv_bfloat16 lx = __float2bfloat16(rx), ly = __float2bfloat16(ry);
    return (uint32_t)__bfloat16_as_ushort(lx) | ((uint32_t)__bfloat16_as_ushort(ly) << 16);
}

// ---------------- software grid barrier ----------------
__device__ __forceinline__ void grid_bar() {
    __syncthreads();
    if (threadIdx.x == 0) {
        unsigned gen = *(volatile unsigned*)&g_bar_phase;
        __threadfence();
        unsigned t = atomicAdd(&g_bar_arrive, 1u);
        if (t == NBLK - 1u) {
            *(volatile unsigned*)&g_bar_arrive = 0u;
            __threadfence();
            *(volatile unsigned*)&g_bar_phase = gen + 1u;
        } else {
            while (*(volatile unsigned*)&g_bar_phase == gen) {}
            __threadfence();
        }
    }
    __syncthreads();
}

// ---------------- init: misc + Whh int8 B-frags + W_ih bf16 B-frags ----------------
__global__ void init_kernel(const float* __restrict__ Wih, const float* __restrict__ Whh) {
    int idx = blockIdx.x * blockDim.x + threadIdx.x;   // 0 .. 4194303
    if (idx < Bn) g_ptag[idx] = START_I;
    if (idx == 0) { g_loss = 0.0; g_bar_arrive = 0u; g_ptag_ready = 0u; }
    if (idx < Tn * G4n) {
        int t = idx >> 12;
        int n = idx & (G4n - 1);
        g_Wtag[idx] = Wih[(size_t)n * DTn + Hn + t];
    }
    if (idx < 524288) {   // Whh int8 B-frags: idx = ((bid*4+nt)*32+kt)*32+lane  (R12-verified)
        int lane = idx & 31;
        int kt   = (idx >> 5) & 31;
        int nt   = (idx >> 10) & 3;
        int bid  = idx >> 12;
        int g = lane >> 2, t = lane & 3;
        int n = nt * 1024 + bid * 8 + g;
        const float* W = Whh + (size_t)n * Hn + kt * 32;
        uint32_t bh0 = 0, bh1 = 0, bl0 = 0, bl1 = 0;
#pragma unroll
        for (int i = 0; i < 4; i++) {
            int w19a = __float2int_rn(W[4 * t + i] * 524288.f);
            int w19b = __float2int_rn(W[16 + 4 * t + i] * 524288.f);
            int whA = (w19a + 128) >> 8, wlA = w19a - (whA << 8);
            int whB = (w19b + 128) >> 8, wlB = w19b - (whB << 8);
            bh0 |= (uint32_t)(whA & 0xFF) << (8 * i);
            bl0 |= (uint32_t)(wlA & 0xFF) << (8 * i);
            bh1 |= (uint32_t)(whB & 0xFF) << (8 * i);
            bl1 |= (uint32_t)(wlB & 0xFF) << (8 * i);
        }
        g_WB8h[idx] = make_uint2(bh0, bh1);
        g_WB8l[idx] = make_uint2(bl0, bl1);
    }
    if (idx < 1048576) {   // W_ih bf16 B-frags (xproj)
        int lane = idx & 31;
        int kt   = (idx >> 5) & 63;
        int nt2  = idx >> 11;
        int g = lane >> 2, tig = lane & 3;
        int n = nt2 * 8 + g;
        int k0 = kt * 16 + 2 * tig;
        const float* W = Wih + (size_t)n * DTn;
        float a = W[k0], b = W[k0 + 1], c = W[k0 + 8], d = W[k0 + 9];
        g_wfh[idx] = make_uint2(pack_bf16_hi(a, b), pack_bf16_hi(c, d));
        g_wfl[idx] = make_uint2(pack_bf16_lo(a, b), pack_bf16_lo(c, d));
    }
}

// ---------------- x -> A-fragment hi/lo bf16 (one-time, xproj) ----------------
__global__ void xprep_kernel(const float* __restrict__ x) {
    int idx = blockIdx.x * blockDim.x + threadIdx.x;
    int lane = idx & 31;
    int kt = (idx >> 5) & 63;
    int mt = idx >> 11;
    int g = lane >> 2, tig = lane & 3;
    int m0 = mt * 16 + g;
    int m1 = m0 + 8;
    int k0 = kt * 16 + 2 * tig;
    const float* r0 = x + ((size_t)((m0 & 127) * 256 + (m0 >> 7))) * Hn;
    const float* r1 = x + ((size_t)((m1 & 127) * 256 + (m1 >> 7))) * Hn;
    float2 v00 = *(const float2*)(r0 + k0);
    float2 v01 = *(const float2*)(r0 + k0 + 8);
    float2 v10 = *(const float2*)(r1 + k0);
    float2 v11 = *(const float2*)(r1 + k0 + 8);
    g_xh[idx] = make_uint4(pack_bf16_hi(v00.x, v00.y), pack_bf16_hi(v10.x, v10.y),
                           pack_bf16_hi(v01.x, v01.y), pack_bf16_hi(v11.x, v11.y));
    g_xl[idx] = make_uint4(pack_bf16_lo(v00.x, v00.y), pack_bf16_lo(v10.x, v10.y),
                           pack_bf16_lo(v01.x, v01.y), pack_bf16_lo(v11.x, v11.y));
}

// ---------------- phase 1: x-projection via HMMA bf16 3-split (R10, unchanged) ----------------
__global__ __launch_bounds__(256) void xproj_kernel(
    const float* __restrict__ bih, const float* __restrict__ bhh)
{
    const int tid = threadIdx.x;
    const int wid = tid >> 5, lane = tid & 31;
    const int g = lane >> 2, tig = lane & 3;
    const int wm = wid & 1, wn = wid >> 1;
    const int mt0 = blockIdx.y * 8 + wm * 4;
    const int nt0 = blockIdx.x * 16 + wn * 4;

    const uint4* Ah = g_xh + (size_t)mt0 * 2048 + lane;
    const uint4* Al = g_xl + (size_t)mt0 * 2048 + lane;
    const uint2* Bh = g_wfh + (size_t)nt0 * 2048 + lane;
    const uint2* Bl = g_wfl + (size_t)nt0 * 2048 + lane;

    float dacc[4][4][4];
#pragma unroll
    for (int i = 0; i < 4; i++)
#pragma unroll
        for (int j = 0; j < 4; j++)
#pragma unroll
            for (int e = 0; e < 4; e++) dacc[i][j][e] = 0.f;

    uint4 ah[4], al[4]; uint2 bh[4], bl[4];
#pragma unroll
    for (int i = 0; i < 4; i++) { ah[i] = __ldg(Ah + i * 2048); al[i] = __ldg(Al + i * 2048); }
#pragma unroll
    for (int j = 0; j < 4; j++) { bh[j] = __ldg(Bh + j * 2048); bl[j] = __ldg(Bl + j * 2048); }

    for (int kt = 0; kt < 64; kt++) {
        uint4 ahn[4], aln[4]; uint2 bhn[4], bln[4];
        if (kt < 63) {
#pragma unroll
            for (int i = 0; i < 4; i++) {
                ahn[i] = __ldg(Ah + i * 2048 + (kt + 1) * 32);
                aln[i] = __ldg(Al + i * 2048 + (kt + 1) * 32);
            }
#pragma unroll
            for (int j = 0; j < 4; j++) {
                bhn[j] = __ldg(Bh + j * 2048 + (kt + 1) * 32);
                bln[j] = __ldg(Bl + j * 2048 + (kt + 1) * 32);
            }
        }
#pragma unroll
        for (int i = 0; i < 4; i++)
#pragma unroll
            for (int j = 0; j < 4; j++)
                mma_bf16(dacc[i][j], ah[i].x, ah[i].y, ah[i].z, ah[i].w, bh[j].x, bh[j].y);
#pragma unroll
        for (int i = 0; i < 4; i++)
#pragma unroll
            for (int j = 0; j < 4; j++)
                mma_bf16(dacc[i][j], al[i].x, al[i].y, al[i].z, al[i].w, bh[j].x, bh[j].y);
#pragma unroll
        for (int i = 0; i < 4; i++)
#pragma unroll
            for (int j = 0; j < 4; j++)
                mma_bf16(dacc[i][j], ah[i].x, ah[i].y, ah[i].z, ah[i].w, bl[j].x, bl[j].y);
#pragma unroll
        for (int i = 0; i < 4; i++) { ah[i] = ahn[i]; al[i] = aln[i]; }
#pragma unroll
        for (int j = 0; j < 4; j++) { bh[j] = bhn[j]; bl[j] = bln[j]; }
    }

#pragma unroll
    for (int j = 0; j < 4; j++) {
        int n = (nt0 + j) * 8 + 2 * tig;
        float b0 = bih[n] + bhh[n];
        float b1 = bih[n + 1] + bhh[n + 1];
#pragma unroll
        for (int i = 0; i < 4; i++) {
            int m = (mt0 + i) * 16 + g;
            *(float2*)(g_G + (size_t)m * G4n + n) =
                make_float2(dacc[i][j][0] + b0, dacc[i][j][1] + b1);
            *(float2*)(g_G + (size_t)(m + 8) * G4n + n) =
                make_float2(dacc[i][j][2] + b0, dacc[i][j][3] + b1);
        }
    }
}

// ---------------- int8 GEMM slice (R12-verified math), constant trip count ----------------
template<int KCNT>
__device__ __forceinline__ void gemm_i8(float (*pf)[4],
    const uint4* __restrict__ Ah4, const uint4* __restrict__ Al4,
    const uint2* __restrict__ BH, const uint2* __restrict__ BL,
    int ktbase, int lane)
{
    int acch[4][4], accm[4][4];
#pragma unroll
    for (int nt = 0; nt < 4; nt++)
#pragma unroll
        for (int e = 0; e < 4; e++) { acch[nt][e] = 0; accm[nt][e] = 0; }

    uint4 ahs[3], als[3];
#pragma unroll
    for (int d = 0; d < 3; d++) {
        ahs[d] = __ldcg(Ah4 + d * 32);
        als[d] = __ldcg(Al4 + d * 32);
    }
#pragma unroll
    for (int ktl = 0; ktl < KCNT; ktl++) {
        const int sl = ktl % 3;
        uint4 ah = ahs[sl], al = als[sl];
        if (ktl + 3 < KCNT) {
            ahs[sl] = __ldcg(Ah4 + (ktl + 3) * 32);
            als[sl] = __ldcg(Al4 + (ktl + 3) * 32);
        }
        const int kt = ktbase + ktl;
        uint2 bh0 = BH[(0 * 32 + kt) * 32 + lane];
        uint2 bh1 = BH[(1 * 32 + kt) * 32 + lane];
        uint2 bh2 = BH[(2 * 32 + kt) * 32 + lane];
        uint2 bh3 = BH[(3 * 32 + kt) * 32 + lane];
        imma(acch[0], ah.x, ah.y, ah.z, ah.w, bh0.x, bh0.y);
        imma(acch[1], ah.x, ah.y, ah.z, ah.w, bh1.x, bh1.y);
        imma(acch[2], ah.x, ah.y, ah.z, ah.w, bh2.x, bh2.y);
        imma(acch[3], ah.x, ah.y, ah.z, ah.w, bh3.x, bh3.y);
        uint2 bl0 = BL[(0 * 32 + kt) * 32 + lane];
        uint2 bl1 = BL[(1 * 32 + kt) * 32 + lane];
        uint2 bl2 = BL[(2 * 32 + kt) * 32 + lane];
        uint2 bl3 = BL[(3 * 32 + kt) * 32 + lane];
        imma(accm[0], ah.x, ah.y, ah.z, ah.w, bl0.x, bl0.y);
        imma(accm[1], ah.x, ah.y, ah.z, ah.w, bl1.x, bl1.y);
        imma(accm[2], ah.x, ah.y, ah.z, ah.w, bl2.x, bl2.y);
        imma(accm[3], ah.x, ah.y, ah.z, ah.w, bl3.x, bl3.y);
        imma(accm[0], al.x, al.y, al.z, al.w, bh0.x, bh0.y);
        imma(accm[1], al.x, al.y, al.z, al.w, bh1.x, bh1.y);
        imma(accm[2], al.x, al.y, al.z, al.w, bh2.x, bh2.y);
        imma(accm[3], al.x, al.y, al.z, al.w, bh3.x, bh3.y);
    }
#pragma unroll
    for (int nt = 0; nt < 4; nt++)
#pragma unroll
        for (int e = 0; e < 4; e++)
            pf[nt][e] = (float)acch[nt][e] * 65536.f + (float)accm[nt][e] * 256.f;
}

// ---------------- persistent loop: int8 split-K + warp-specialized logits ----------------
// smem: [0..1024) red, [1024..33792) WB8h, [33792..66560) WB8l, [66560..82944) red2
#define LOOP_SMEM 82944
#define KT0 20
#define KT1 12

__global__ __launch_bounds__(512, 1) void loop_kernel(
    const float* __restrict__ Wout, const float* __restrict__ bout,
    const int* __restrict__ tags, const int* __restrict__ mask,
    float* __restrict__ out)
{
    extern __shared__ __align__(16) unsigned char smem[];
    float* red = (float*)smem;
    const uint2* BH = (const uint2*)(smem + 1024);
    const uint2* BL = (const uint2*)(smem + 33792);
    float* red2 = (float*)(smem + 66560);   // [16][256]

    const int bid = blockIdx.x;
    const int tid = threadIdx.x;
    const int wid = tid >> 5;
    const int lane = tid & 31;
    const int g = lane >> 2, tig = lane & 3;
    const int wk = wid >> 3;
    const int wm = wid & 7;
    const int gtid = tid & 255;

    {
        const uint2* srcH = g_WB8h + (size_t)bid * 4096;
        const uint2* srcL = g_WB8l + (size_t)bid * 4096;
        uint2* dstH = (uint2*)(smem + 1024);
        uint2* dstL = (uint2*)(smem + 33792);
        for (int u = tid; u < 4096; u += 512) { dstH[u] = srcH[u]; dstL[u] = srcL[u]; }
    }
    __syncthreads();

    const int b1 = wm * 16 + g;
    const int b2 = b1 + 8;
    const int kkg0 = bid * 8 + 2 * tig;
    const int ktbase = wk ? KT0 : 0;

    // epilogue A-frag store offsets (R12-verified)
    const int ku = ((bid & 3) << 3) + 2 * tig;
    const int ktA = bid >> 2;
    const int half = ku >> 4, kq = (ku >> 2) & 3, kb = ku & 3;
    const int lanep = g * 4 + kq;
    const int offA = (((b1 >> 4) * 32 + ktA) * 32 + lanep) * 16 + (half * 2 + ((b1 >> 3) & 1)) * 4 + kb;
    const int offB = (((b2 >> 4) * 32 + ktA) * 32 + lanep) * 16 + (half * 2 + ((b2 >> 3) & 1)) * 4 + kb;

    const float invS = 1.0f / (32512.0f * 524288.0f);

    float creg[2][2] = {{0.f, 0.f}, {0.f, 0.f}};
    double lossAcc = 0.0;

    // logits for step ls (h(ls) in g_h[(ls+1)&1]); wk1 threads only (R10-proven).
    auto do_logits = [&](int ls, bool feed) {
        const float4* h4 = (const float4*)(g_h[(ls + 1) & 1] + bid * Hn);
        float4 hvv = __ldcg(h4 + gtid);
        const float4* W4 = (const float4*)Wout;
        float p[Tn];
#pragma unroll
        for (int t = 0; t < Tn; t++) {
            float4 w = __ldg(W4 + t * 256 + gtid);
            p[t] = hvv.x * w.x + hvv.y * w.y + hvv.z * w.z + hvv.w * w.w;
        }
#pragma unroll
        for (int t = 0; t < Tn; t++) {
#pragma unroll
            for (int o = 16; o > 0; o >>= 1)
                p[t] += __shfl_xor_sync(0xffffffffu, p[t], o);
        }
        if (lane == 0) {
#pragma unroll
            for (int t = 0; t < Tn; t++) red[(gtid >> 5) * Tn + t] = p[t];
        }
        asm volatile("bar.sync 1, 256;" ::: "memory");
        if (gtid < 32) {
            float l = -3.402823466e38f;
            if (gtid < Tn) {
                l = bout[gtid];
#pragma unroll
                for (int w = 0; w < 8; w++) l += red[w * Tn + gtid];
            }
            float v = l; int idx = gtid;
#pragma unroll
            for (int o = 16; o > 0; o >>= 1) {
                float v2 = __shfl_xor_sync(0xffffffffu, v, o);
                int   i2 = __shfl_xor_sync(0xffffffffu, idx, o);
                if (v2 > v || (v2 == v && i2 < idx)) { v = v2; idx = i2; }
            }
            if (feed && gtid == 0) g_ptag[bid] = idx;
            if (mask[bid * Sn + ls] != 0) {
                float e = (gtid < Tn) ? expf(l - v) : 0.f;
#pragma unroll
                for (int o = 16; o > 0; o >>= 1)
                    e += __shfl_xor_sync(0xffffffffu, e, o);
                int y = tags[bid * Sn + ls];
                float ly = __shfl_sync(0xffffffffu, l, y);
                if (gtid == 0) lossAcc += (double)(v + logf(e) - ly);
            }
            if (feed && gtid == 0) {
                __threadfence();
                atomicAdd(&g_ptag_ready, 1u);
            }
        }
    };

    for (int s = 0; s < Sn; s++) {
        float2 Gv[2][4];
        if (tid < 256) {
#pragma unroll
            for (int r2 = 0; r2 < 2; r2++) {
                int r = r2 ? b2 : b1;
                const float* Gp = g_G + (size_t)(s * Bn + r) * G4n + kkg0;
#pragma unroll
                for (int nt = 0; nt < 4; nt++)
                    Gv[r2][nt] = __ldcs((const float2*)(Gp + nt * 1024));
            }
        }

        float pf[4][4];
#pragma unroll
        for (int nt = 0; nt < 4; nt++)
#pragma unroll
            for (int e = 0; e < 4; e++) pf[nt][e] = 0.f;

        if (s > 0) {
            if (wk == 1) do_logits(s - 1, true);   // overlaps wk0's GEMM

            const int par = s & 1;
            const uint4* Ah4 = (const uint4*)g_hA8h[par] + (wm * 1024 + ktbase * 32 + lane);
            const uint4* Al4 = (const uint4*)g_hA8l[par] + (wm * 1024 + ktbase * 32 + lane);
            if (wk == 0) gemm_i8<KT0>(pf, Ah4, Al4, BH, BL, 0, lane);
            else         gemm_i8<KT1>(pf, Ah4, Al4, BH, BL, KT0, lane);
        }

        // split-K: wk1 publishes, threads 0-255 accumulate
        if (wk == 1) {
#pragma unroll
            for (int nt = 0; nt < 4; nt++)
#pragma unroll
                for (int e = 0; e < 4; e++)
                    red2[(nt * 4 + e) * 256 + gtid] = pf[nt][e];
        }
        __syncthreads();
        if (tid < 256) {
#pragma unroll
            for (int nt = 0; nt < 4; nt++)
#pragma unroll
                for (int e = 0; e < 4; e++)
                    pf[nt][e] += red2[(nt * 4 + e) * 256 + tid];
        }

        if (s > 0) {
            if (tid == 0) {
                while (*(volatile unsigned*)&g_ptag_ready < (unsigned)s * 128u) {}
            }
            __syncthreads();
        }

        // ---- epilogue (threads 0-255) ----
        const int po = (s & 1) ^ 1;
        if (tid < 256) {
            int pt1 = __ldcg(&g_ptag[b1]);
            int pt2 = __ldcg(&g_ptag[b2]);
            const float* W1 = g_Wtag + pt1 * G4n + kkg0;
            const float* W2 = g_Wtag + pt2 * G4n + kkg0;
#pragma unroll
            for (int r2 = 0; r2 < 2; r2++) {
                int r = r2 ? b2 : b1;
                const float* Wt = r2 ? W2 : W1;
                float h01[2];
#pragma unroll
                for (int e = 0; e < 2; e++) {
                    int de = r2 * 2 + e;
                    float G0 = e ? Gv[r2][0].y : Gv[r2][0].x;
                    float G1 = e ? Gv[r2][1].y : Gv[r2][1].x;
                    float G2 = e ? Gv[r2][2].y : Gv[r2][2].x;
                    float G3 = e ? Gv[r2][3].y : Gv[r2][3].x;
                    float gi = pf[0][de] * invS + G0 + Wt[e];
                    float gf = pf[1][de] * invS + G1 + Wt[1024 + e];
                    float gg = pf[2][de] * invS + G2 + Wt[2048 + e];
                    float go = pf[3][de] * invS + G3 + Wt[3072 + e];
                    gi = 1.f / (1.f + __expf(-gi));
                    gf = 1.f / (1.f + __expf(-gf));
                    gg = tanhf(gg);
                    go = 1.f / (1.f + __expf(-go));
                    creg[r2][e] = gf * creg[r2][e] + gi * gg;
                    h01[e] = go * tanhf(creg[r2][e]);
                }
                *(float2*)(g_h[po] + r * Hn + kkg0) = make_float2(h01[0], h01[1]);
                int h16a = __float2int_rn(h01[0] * 32512.f);
                int h16b = __float2int_rn(h01[1] * 32512.f);
                int ahiA = (h16a + 128) >> 8, aloA = h16a - (ahiA << 8);
                int ahiB = (h16b + 128) >> 8, aloB = h16b - (ahiB << 8);
                unsigned short sh = (unsigned short)((ahiA & 0xFF) | ((ahiB & 0xFF) << 8));
                unsigned short slv = (unsigned short)((aloA & 0xFF) | ((aloB & 0xFF) << 8));
                int off = r2 ? offB : offA;
                *(unsigned short*)(g_hA8h[po] + off) = sh;
                *(unsigned short*)(g_hA8l[po] + off) = slv;
            }
        }
        grid_bar();
    }

    // tail: logits(255) (loss only)
    if (wk == 1) do_logits(Sn - 1, false);
    if (tid == 256) atomicAdd(&g_loss, lossAcc);
    grid_bar();
    if (bid == 0 && tid == 0) out[0] = (float)(*(volatile double*)&g_loss);
}

// ---------------- launch ----------------
extern "C" void kernel_launch(void* const* d_in, const int* in_sizes, int n_in,
                              void* d_out, int out_size)
{
    const float *x = nullptr, *Wih = nullptr, *Whh = nullptr;
    const float *bih = nullptr, *bhh = nullptr, *Wout = nullptr, *bout = nullptr;
    const int *tags = nullptr, *maskp = nullptr;
    for (int i = 0; i < n_in; i++) {
        int sz = in_sizes[i];
        const void* p = d_in[i];
        switch (sz) {
            case 33554432: x = (const float*)p; break;
            case 4276224:  Wih = (const float*)p; break;
            case 4194304:  Whh = (const float*)p; break;
            case 4096:     if (!bih) bih = (const float*)p; else bhh = (const float*)p; break;
            case 32768:    if (!tags) tags = (const int*)p; else maskp = (const int*)p; break;
            case 20480:    Wout = (const float*)p; break;
            case 20:       bout = (const float*)p; break;
            default: break;
        }
    }

    cudaFuncSetAttribute(loop_kernel, cudaFuncAttributeMaxDynamicSharedMemorySize, LOOP_SMEM);

    init_kernel<<<16384, 256>>>(Wih, Whh);                               // #1
    xprep_kernel<<<16384, 256>>>(x);                                     // #2
    xproj_kernel<<<dim3(32, 256), 256>>>(bih, bhh);                      // #3
    loop_kernel<<<NBLK, 512, LOOP_SMEM>>>(Wout, bout, tags, maskp, (float*)d_out);  // #4 (profiled)
}

// round 14
// speedup vs baseline: 1.4845x; 1.3863x over previous
#include <cuda_runtime.h>
#include <cuda_bf16.h>
#include <cstdint>

#define Bn 128
#define Sn 256
#define Hn 1024
#define Tn 20
#define G4n 4096
#define DTn 1044
#define START_I 19
#define NBLK 128u

typedef unsigned long long u64t;

// ---------------- device scratch ----------------
__device__ float g_G[(size_t)Sn * Bn * G4n];                 // x-projection + biases (fp32)
__device__ float g_h[2][Bn * Hn];                            // fp32 h (for logits)
__device__ float g_Wtag[Tn * G4n];                           // one-hot columns of W_ih
__device__ __align__(16) u64t g_Bfrag[2097152];              // Whh bf16 hi/lo B-frags (16MB)
__device__ __align__(16) uint32_t g_hAh[2][65536];           // h bf16-hi A-frags (ping-pong)
__device__ __align__(16) uint32_t g_hAl[2][65536];           // h bf16-lo residual
__device__ __align__(16) uint4 g_xh[4194304];                // x bf16-hi A-frags (67MB)
__device__ __align__(16) uint4 g_xl[4194304];                // x bf16-lo A-frags (67MB)
__device__ __align__(16) uint2 g_wfh[1048576];               // W_ih bf16-hi B-frags (8MB)
__device__ __align__(16) uint2 g_wfl[1048576];               // W_ih bf16-lo B-frags (8MB)
__device__ int   g_ptag[Bn];
__device__ int   g_hdone[NBLK];                              // per-block h-published flag (step+1)
__device__ int   g_ldone[NBLK];                              // per-block logits-published flag (step+1)
__device__ double g_loss;

// ---------------- HMMA bf16 ----------------
__device__ __forceinline__ void mma_bf16(float* d,
    uint32_t a0, uint32_t a1, uint32_t a2, uint32_t a3,
    uint32_t b0, uint32_t b1)
{
    asm volatile(
        "mma.sync.aligned.m16n8k16.row.col.f32.bf16.bf16.f32 "
        "{%0,%1,%2,%3}, {%4,%5,%6,%7}, {%8,%9}, {%0,%1,%2,%3};"
        : "+f"(d[0]), "+f"(d[1]), "+f"(d[2]), "+f"(d[3])
        : "r"(a0), "r"(a1), "r"(a2), "r"(a3), "r"(b0), "r"(b1));
}
__device__ __forceinline__ uint32_t pack_bf16_hi(float x, float y) {
    __nv_bfloat16 bx = __float2bfloat16(x), by = __float2bfloat16(y);
    return (uint32_t)__bfloat16_as_ushort(bx) | ((uint32_t)__bfloat16_as_ushort(by) << 16);
}
__device__ __forceinline__ uint32_t pack_bf16_lo(float x, float y) {
    __nv_bfloat16 bx = __float2bfloat16(x), by = __float2bfloat16(y);
    float rx = x - __bfloat162float(bx), ry = y - __bfloat162float(by);
    __nv_bfloat16 lx = __float2bfloat16(rx), ly = __float2bfloat16(ry);
    return (uint32_t)__bfloat16_as_ushort(lx) | ((uint32_t)__bfloat16_as_ushort(ly) << 16);
}

// ---------------- init ----------------
__global__ void init_kernel(const float* __restrict__ Wih, const float* __restrict__ Whh) {
    int idx = blockIdx.x * blockDim.x + threadIdx.x;   // 0 .. 4194303
    if (idx < Bn) g_ptag[idx] = START_I;
    if (idx < (int)NBLK) { g_hdone[idx] = 0; g_ldone[idx] = 0; }
    if (idx == 0) g_loss = 0.0;
    if (idx < Tn * G4n) {
        int t = idx >> 12;
        int n = idx & (G4n - 1);
        g_Wtag[idx] = Wih[(size_t)n * DTn + Hn + t];
    }
    if (idx < 2097152) {   // Whh B-frags (loop kernel)
        int lane  = idx & 31;
        int kt    = (idx >> 5) & 63;
        int nt    = (idx >> 11) & 3;
        int which = (idx >> 13) & 1;
        int bid   = idx >> 14;
        int g = lane >> 2, tig = lane & 3;
        int n = nt * 1024 + bid * 8 + g;
        int k0 = kt * 16 + 2 * tig;
        const float* W = Whh + (size_t)n * Hn;
        float v00 = W[k0], v01 = W[k0 + 1], v10 = W[k0 + 8], v11 = W[k0 + 9];
        uint32_t r0, r1;
        if (which == 0) { r0 = pack_bf16_hi(v00, v01); r1 = pack_bf16_hi(v10, v11); }
        else            { r0 = pack_bf16_lo(v00, v01); r1 = pack_bf16_lo(v10, v11); }
        g_Bfrag[idx] = (u64t)r0 | ((u64t)r1 << 32);
    }
    if (idx < 1048576) {   // W_ih B-frags (xproj)
        int lane = idx & 31;
        int kt   = (idx >> 5) & 63;
        int nt2  = idx >> 11;
        int g = lane >> 2, tig = lane & 3;
        int n = nt2 * 8 + g;
        int k0 = kt * 16 + 2 * tig;
        const float* W = Wih + (size_t)n * DTn;
        float a = W[k0], b = W[k0 + 1], c = W[k0 + 8], d = W[k0 + 9];
        g_wfh[idx] = make_uint2(pack_bf16_hi(a, b), pack_bf16_hi(c, d));
        g_wfl[idx] = make_uint2(pack_bf16_lo(a, b), pack_bf16_lo(c, d));
    }
}

// ---------------- x -> A-fragment hi/lo bf16 (one-time) ----------------
__global__ void xprep_kernel(const float* __restrict__ x) {
    int idx = blockIdx.x * blockDim.x + threadIdx.x;
    int lane = idx & 31;
    int kt = (idx >> 5) & 63;
    int mt = idx >> 11;
    int g = lane >> 2, tig = lane & 3;
    int m0 = mt * 16 + g;
    int m1 = m0 + 8;
    int k0 = kt * 16 + 2 * tig;
    const float* r0 = x + ((size_t)((m0 & 127) * 256 + (m0 >> 7))) * Hn;
    const float* r1 = x + ((size_t)((m1 & 127) * 256 + (m1 >> 7))) * Hn;
    float2 v00 = *(const float2*)(r0 + k0);
    float2 v01 = *(const float2*)(r0 + k0 + 8);
    float2 v10 = *(const float2*)(r1 + k0);
    float2 v11 = *(const float2*)(r1 + k0 + 8);
    g_xh[idx] = make_uint4(pack_bf16_hi(v00.x, v00.y), pack_bf16_hi(v10.x, v10.y),
                           pack_bf16_hi(v01.x, v01.y), pack_bf16_hi(v11.x, v11.y));
    g_xl[idx] = make_uint4(pack_bf16_lo(v00.x, v00.y), pack_bf16_lo(v10.x, v10.y),
                           pack_bf16_lo(v01.x, v01.y), pack_bf16_lo(v11.x, v11.y));
}

// ---------------- phase 1: x-projection via HMMA bf16 3-split (R10, unchanged) ----------------
__global__ __launch_bounds__(256) void xproj_kernel(
    const float* __restrict__ bih, const float* __restrict__ bhh)
{
    const int tid = threadIdx.x;
    const int wid = tid >> 5, lane = tid & 31;
    const int g = lane >> 2, tig = lane & 3;
    const int wm = wid & 1, wn = wid >> 1;
    const int mt0 = blockIdx.y * 8 + wm * 4;
    const int nt0 = blockIdx.x * 16 + wn * 4;

    const uint4* Ah = g_xh + (size_t)mt0 * 2048 + lane;
    const uint4* Al = g_xl + (size_t)mt0 * 2048 + lane;
    const uint2* Bh = g_wfh + (size_t)nt0 * 2048 + lane;
    const uint2* Bl = g_wfl + (size_t)nt0 * 2048 + lane;

    float dacc[4][4][4];
#pragma unroll
    for (int i = 0; i < 4; i++)
#pragma unroll
        for (int j = 0; j < 4; j++)
#pragma unroll
            for (int e = 0; e < 4; e++) dacc[i][j][e] = 0.f;

    uint4 ah[4], al[4]; uint2 bh[4], bl[4];
#pragma unroll
    for (int i = 0; i < 4; i++) { ah[i] = __ldg(Ah + i * 2048); al[i] = __ldg(Al + i * 2048); }
#pragma unroll
    for (int j = 0; j < 4; j++) { bh[j] = __ldg(Bh + j * 2048); bl[j] = __ldg(Bl + j * 2048); }

    for (int kt = 0; kt < 64; kt++) {
        uint4 ahn[4], aln[4]; uint2 bhn[4], bln[4];
        if (kt < 63) {
#pragma unroll
            for (int i = 0; i < 4; i++) {
                ahn[i] = __ldg(Ah + i * 2048 + (kt + 1) * 32);
                aln[i] = __ldg(Al + i * 2048 + (kt + 1) * 32);
            }
#pragma unroll
            for (int j = 0; j < 4; j++) {
                bhn[j] = __ldg(Bh + j * 2048 + (kt + 1) * 32);
                bln[j] = __ldg(Bl + j * 2048 + (kt + 1) * 32);
            }
        }
#pragma unroll
        for (int i = 0; i < 4; i++)
#pragma unroll
            for (int j = 0; j < 4; j++)
                mma_bf16(dacc[i][j], ah[i].x, ah[i].y, ah[i].z, ah[i].w, bh[j].x, bh[j].y);
#pragma unroll
        for (int i = 0; i < 4; i++)
#pragma unroll
            for (int j = 0; j < 4; j++)
                mma_bf16(dacc[i][j], al[i].x, al[i].y, al[i].z, al[i].w, bh[j].x, bh[j].y);
#pragma unroll
        for (int i = 0; i < 4; i++)
#pragma unroll
            for (int j = 0; j < 4; j++)
                mma_bf16(dacc[i][j], ah[i].x, ah[i].y, ah[i].z, ah[i].w, bl[j].x, bl[j].y);
#pragma unroll
        for (int i = 0; i < 4; i++) { ah[i] = ahn[i]; al[i] = aln[i]; }
#pragma unroll
        for (int j = 0; j < 4; j++) { bh[j] = bhn[j]; bl[j] = bln[j]; }
    }

#pragma unroll
    for (int j = 0; j < 4; j++) {
        int n = (nt0 + j) * 8 + 2 * tig;
        float b0 = bih[n] + bhh[n];
        float b1 = bih[n + 1] + bhh[n + 1];
#pragma unroll
        for (int i = 0; i < 4; i++) {
            int m = (mt0 + i) * 16 + g;
            *(float2*)(g_G + (size_t)m * G4n + n) =
                make_float2(dacc[i][j][0] + b0, dacc[i][j][1] + b1);
            *(float2*)(g_G + (size_t)(m + 8) * G4n + n) =
                make_float2(dacc[i][j][2] + b0, dacc[i][j][3] + b1);
        }
    }
}

// ---------------- GEMM slice: R8/R10-proven body, constant trip count ----------------
template<int KCNT>
__device__ __forceinline__ void gemm_part(float (*dacc)[4],
    const uint4* __restrict__ Ah4, const uint4* __restrict__ Al4,
    const uint2* __restrict__ Bh, const uint2* __restrict__ Bl,
    int ktbase, int lane)
{
    uint4 ahs[3], als[3];
#pragma unroll
    for (int d = 0; d < 3; d++) {
        ahs[d] = __ldcg(Ah4 + d * 32);
        als[d] = __ldcg(Al4 + d * 32);
    }
#pragma unroll
    for (int ktl = 0; ktl < KCNT; ktl++) {
        const int sl = ktl % 3;
        uint4 ah = ahs[sl], al = als[sl];
        if (ktl + 3 < KCNT) {
            ahs[sl] = __ldcg(Ah4 + (ktl + 3) * 32);
            als[sl] = __ldcg(Al4 + (ktl + 3) * 32);
        }
        const int kt = ktbase + ktl;
        uint2 b0 = Bh[(0 * 64 + kt) * 32 + lane];
        uint2 b1r = Bh[(1 * 64 + kt) * 32 + lane];
        uint2 b2r = Bh[(2 * 64 + kt) * 32 + lane];
        uint2 b3 = Bh[(3 * 64 + kt) * 32 + lane];
        mma_bf16(dacc[0], ah.x, ah.y, ah.z, ah.w, b0.x, b0.y);
        mma_bf16(dacc[1], ah.x, ah.y, ah.z, ah.w, b1r.x, b1r.y);
        mma_bf16(dacc[2], ah.x, ah.y, ah.z, ah.w, b2r.x, b2r.y);
        mma_bf16(dacc[3], ah.x, ah.y, ah.z, ah.w, b3.x, b3.y);
        mma_bf16(dacc[0], al.x, al.y, al.z, al.w, b0.x, b0.y);
        mma_bf16(dacc[1], al.x, al.y, al.z, al.w, b1r.x, b1r.y);
        mma_bf16(dacc[2], al.x, al.y, al.z, al.w, b2r.x, b2r.y);
        mma_bf16(dacc[3], al.x, al.y, al.z, al.w, b3.x, b3.y);
        b0 = Bl[(0 * 64 + kt) * 32 + lane];
        b1r = Bl[(1 * 64 + kt) * 32 + lane];
        b2r = Bl[(2 * 64 + kt) * 32 + lane];
        b3 = Bl[(3 * 64 + kt) * 32 + lane];
        mma_bf16(dacc[0], ah.x, ah.y, ah.z, ah.w, b0.x, b0.y);
        mma_bf16(dacc[1], ah.x, ah.y, ah.z, ah.w, b1r.x, b1r.y);
        mma_bf16(dacc[2], ah.x, ah.y, ah.z, ah.w, b2r.x, b2r.y);
        mma_bf16(dacc[3], ah.x, ah.y, ah.z, ah.w, b3.x, b3.y);
    }
}

// ---------------- persistent loop: R10 + flag-based barriers ----------------
#define LOOP_SMEM 148480
#define KT0 40
#define KT1 24

__global__ __launch_bounds__(512, 1) void loop_kernel(
    const float* __restrict__ Wout, const float* __restrict__ bout,
    const int* __restrict__ tags, const int* __restrict__ mask,
    float* __restrict__ out)
{
    extern __shared__ __align__(16) unsigned char smem[];
    float* red = (float*)smem;
    const uint2* Bh = (const uint2*)(smem + 1024);
    const uint2* Bl = (const uint2*)(smem + 1024 + 65536);
    float* red2 = (float*)(smem + 132096);   // [16][256]

    const int bid = blockIdx.x;
    const int tid = threadIdx.x;
    const int wid = tid >> 5;
    const int lane = tid & 31;
    const int g = lane >> 2, tig = lane & 3;
    const int wk = wid >> 3;
    const int wm = wid & 7;
    const int gtid = tid & 255;

    {
        const uint4* src = (const uint4*)g_Bfrag + (size_t)bid * 8192;
        uint4* dst = (uint4*)(smem + 1024);
        for (int u = tid; u < 8192; u += 512) dst[u] = src[u];
    }
    __syncthreads();

    const int b1 = wm * 16 + g;
    const int b2 = b1 + 8;
    const int kkg0 = bid * 8 + 2 * tig;
    const int ktbase = wk ? KT0 : 0;

    float creg[2][2] = {{0.f, 0.f}, {0.f, 0.f}};
    double lossAcc = 0.0;

    // logits for step ls (h(ls) in g_h[(ls+1)&1]); wk1 threads only.
    auto do_logits = [&](int ls, bool feed) {
        const float4* h4 = (const float4*)(g_h[(ls + 1) & 1] + bid * Hn);
        float4 hvv = __ldcg(h4 + gtid);
        const float4* W4 = (const float4*)Wout;
        float p[Tn];
#pragma unroll
        for (int t = 0; t < Tn; t++) {
            float4 w = __ldg(W4 + t * 256 + gtid);
            p[t] = hvv.x * w.x + hvv.y * w.y + hvv.z * w.z + hvv.w * w.w;
        }
#pragma unroll
        for (int t = 0; t < Tn; t++) {
#pragma unroll
            for (int o = 16; o > 0; o >>= 1)
                p[t] += __shfl_xor_sync(0xffffffffu, p[t], o);
        }
        if (lane == 0) {
#pragma unroll
            for (int t = 0; t < Tn; t++) red[(gtid >> 5) * Tn + t] = p[t];
        }
        asm volatile("bar.sync 1, 256;" ::: "memory");
        if (gtid < 32) {
            float l = -3.402823466e38f;
            if (gtid < Tn) {
                l = bout[gtid];
#pragma unroll
                for (int w = 0; w < 8; w++) l += red[w * Tn + gtid];
            }
            float v = l; int idx = gtid;
#pragma unroll
            for (int o = 16; o > 0; o >>= 1) {
                float v2 = __shfl_xor_sync(0xffffffffu, v, o);
                int   i2 = __shfl_xor_sync(0xffffffffu, idx, o);
                if (v2 > v || (v2 == v && i2 < idx)) { v = v2; idx = i2; }
            }
            if (mask[bid * Sn + ls] != 0) {
                float e = (gtid < Tn) ? expf(l - v) : 0.f;
#pragma unroll
                for (int o = 16; o > 0; o >>= 1)
                    e += __shfl_xor_sync(0xffffffffu, e, o);
                int y = tags[bid * Sn + ls];
                float ly = __shfl_sync(0xffffffffu, l, y);
                if (gtid == 0) lossAcc += (double)(v + logf(e) - ly);
            }
            if (feed && gtid == 0) {
                g_ptag[bid] = idx;
                __threadfence();
                *(volatile int*)&g_ldone[bid] = ls + 1;   // flag: logits(ls) published
            }
        }
    };

    for (int s = 0; s < Sn; s++) {
        float2 Gv[2][4];
        if (tid < 256) {
#pragma unroll
            for (int r2 = 0; r2 < 2; r2++) {
                int r = r2 ? b2 : b1;
                const float* Gp = g_G + (size_t)(s * Bn + r) * G4n + kkg0;
#pragma unroll
                for (int nt = 0; nt < 4; nt++)
                    Gv[r2][nt] = __ldcs((const float2*)(Gp + nt * 1024));
            }
        }

        float dacc[4][4];
#pragma unroll
        for (int nt = 0; nt < 4; nt++)
#pragma unroll
            for (int e = 0; e < 4; e++) dacc[nt][e] = 0.f;

        if (s > 0) {
            if (wk == 1) do_logits(s - 1, true);   // overlaps wk0's GEMM

            const int par = s & 1;
            const uint4* Ah4 = (const uint4*)g_hAh[par] + (wm * 2048 + ktbase * 32 + lane);
            const uint4* Al4 = (const uint4*)g_hAl[par] + (wm * 2048 + ktbase * 32 + lane);
            if (wk == 0) gemm_part<KT0>(dacc, Ah4, Al4, Bh, Bl, 0, lane);
            else         gemm_part<KT1>(dacc, Ah4, Al4, Bh, Bl, KT0, lane);
        }

        // split-K: wk1 publishes; then (overlapped) polls logits-done flags
        if (wk == 1) {
#pragma unroll
            for (int nt = 0; nt < 4; nt++)
#pragma unroll
                for (int e = 0; e < 4; e++)
                    red2[(nt * 4 + e) * 256 + gtid] = dacc[nt][e];
            if (s > 0 && gtid < (int)NBLK) {
                while (*(volatile int*)&g_ldone[gtid] < s) {}   // all blocks' logits(s-1) done
            }
        }
        __syncthreads();
        if (tid < 256) {
#pragma unroll
            for (int nt = 0; nt < 4; nt++)
#pragma unroll
                for (int e = 0; e < 4; e++)
                    dacc[nt][e] += red2[(nt * 4 + e) * 256 + tid];
        }

        // ---- epilogue (threads 0-255) ----
        const int po = (s & 1) ^ 1;
        if (tid < 256) {
            int pt1 = __ldcg(&g_ptag[b1]);
            int pt2 = __ldcg(&g_ptag[b2]);
            const float* W1 = g_Wtag + pt1 * G4n + kkg0;
            const float* W2 = g_Wtag + pt2 * G4n + kkg0;
#pragma unroll
            for (int r2 = 0; r2 < 2; r2++) {
                int r = r2 ? b2 : b1;
                const float* Wt = r2 ? W2 : W1;
                float2 wt0 = *(const float2*)(Wt);
                float2 wt1 = *(const float2*)(Wt + 1024);
                float2 wt2 = *(const float2*)(Wt + 2048);
                float2 wt3 = *(const float2*)(Wt + 3072);
                float h01[2];
#pragma unroll
                for (int e = 0; e < 2; e++) {
                    int de = r2 * 2 + e;
                    float G0 = e ? Gv[r2][0].y : Gv[r2][0].x;
                    float G1 = e ? Gv[r2][1].y : Gv[r2][1].x;
                    float G2 = e ? Gv[r2][2].y : Gv[r2][2].x;
                    float G3 = e ? Gv[r2][3].y : Gv[r2][3].x;
                    float gi = dacc[0][de] + G0 + (e ? wt0.y : wt0.x);
                    float gf = dacc[1][de] + G1 + (e ? wt1.y : wt1.x);
                    float gg = dacc[2][de] + G2 + (e ? wt2.y : wt2.x);
                    float go = dacc[3][de] + G3 + (e ? wt3.y : wt3.x);
                    gi = 1.f / (1.f + __expf(-gi));
                    gf = 1.f / (1.f + __expf(-gf));
                    gg = tanhf(gg);
                    go = 1.f / (1.f + __expf(-go));
                    creg[r2][e] = gf * creg[r2][e] + gi * gg;
                    h01[e] = go * tanhf(creg[r2][e]);
                }
                *(float2*)(g_h[po] + r * Hn + kkg0) = make_float2(h01[0], h01[1]);
                int idx = ((r >> 4) * 8192) + ((bid >> 1) * 128)
                        + (((r & 7) * 4 + tig) * 4) + ((r >> 3) & 1) + 2 * (bid & 1);
                g_hAh[po][idx] = pack_bf16_hi(h01[0], h01[1]);
                g_hAl[po][idx] = pack_bf16_lo(h01[0], h01[1]);
            }
        }

        // ---- h barrier: flag publish + distributed poll (replaces grid_bar) ----
        __syncthreads();
        if (tid == 0) {
            __threadfence();
            *(volatile int*)&g_hdone[bid] = s + 1;
        }
        if (tid < (int)NBLK) {
            while (*(volatile int*)&g_hdone[tid] < s + 1) {}
        }
        __syncthreads();
    }

    // tail: logits(255) (loss only), then loss aggregation + output
    if (wk == 1) do_logits(Sn - 1, false);
    __syncthreads();
    if (tid == 256) atomicAdd(&g_loss, lossAcc);
    __syncthreads();
    if (tid == 0) {
        __threadfence();
        *(volatile int*)&g_hdone[bid] = Sn + 1;
    }
    if (bid == 0) {
        if (tid < (int)NBLK) {
            while (*(volatile int*)&g_hdone[tid] < Sn + 1) {}
        }
        __syncthreads();
        if (tid == 0) out[0] = (float)(*(volatile double*)&g_loss);
    }
}

// ---------------- launch ----------------
extern "C" void kernel_launch(void* const* d_in, const int* in_sizes, int n_in,
                              void* d_out, int out_size)
{
    const float *x = nullptr, *Wih = nullptr, *Whh = nullptr;
    const float *bih = nullptr, *bhh = nullptr, *Wout = nullptr, *bout = nullptr;
    const int *tags = nullptr, *maskp = nullptr;
    for (int i = 0; i < n_in; i++) {
        int sz = in_sizes[i];
        const void* p = d_in[i];
        switch (sz) {
            case 33554432: x = (const float*)p; break;
            case 4276224:  Wih = (const float*)p; break;
            case 4194304:  Whh = (const float*)p; break;
            case 4096:     if (!bih) bih = (const float*)p; else bhh = (const float*)p; break;
            case 32768:    if (!tags) tags = (const int*)p; else maskp = (const int*)p; break;
            case 20480:    Wout = (const float*)p; break;
            case 20:       bout = (const float*)p; break;
            default: break;
        }
    }

    cudaFuncSetAttribute(loop_kernel, cudaFuncAttributeMaxDynamicSharedMemorySize, LOOP_SMEM);

    init_kernel<<<16384, 256>>>(Wih, Whh);                               // #1
    xprep_kernel<<<16384, 256>>>(x);                                     // #2
    xproj_kernel<<<dim3(32, 256), 256>>>(bih, bhh);                      // #3
    loop_kernel<<<NBLK, 512, LOOP_SMEM>>>(Wout, bout, tags, maskp, (float*)d_out);  // #4 (profiled)
}

// round 15
// speedup vs baseline: 1.9057x; 1.2837x over previous
#include <cuda_runtime.h>
#include <cuda_bf16.h>
#include <cuda_fp16.h>
#include <cstdint>

#define Bn 128
#define Sn 256
#define Hn 1024
#define Tn 20
#define G4n 4096
#define DTn 1044
#define START_I 19
#define NBLK 128u

typedef unsigned long long u64t;

// ---------------- device scratch ----------------
__device__ float g_G[(size_t)Sn * Bn * G4n];                 // x-projection + biases (fp32)
__device__ float g_h[2][Bn * Hn];                            // fp32 h (for logits)
__device__ float g_Wtag[Tn * G4n];                           // one-hot columns of W_ih
__device__ __align__(16) u64t g_Bfrag[2097152];              // Whh f16 hi/lo B-frags (16MB)
__device__ __align__(16) uint32_t g_hAf[2][65536];           // h fp16 A-frags (ping-pong)
__device__ __align__(16) uint4 g_xh[4194304];                // x bf16-hi A-frags (67MB, xproj)
__device__ __align__(16) uint4 g_xl[4194304];                // x bf16-lo A-frags (67MB)
__device__ __align__(16) uint2 g_wfh[1048576];               // W_ih bf16-hi B-frags (8MB)
__device__ __align__(16) uint2 g_wfl[1048576];               // W_ih bf16-lo B-frags (8MB)
__device__ int   g_ptag[Bn];
__device__ double g_loss;
__device__ unsigned g_bar_arrive, g_bar_phase, g_ptag_ready;

// ---------------- mma wrappers ----------------
__device__ __forceinline__ void mma_bf16(float* d,
    uint32_t a0, uint32_t a1, uint32_t a2, uint32_t a3,
    uint32_t b0, uint32_t b1)
{
    asm volatile(
        "mma.sync.aligned.m16n8k16.row.col.f32.bf16.bf16.f32 "
        "{%0,%1,%2,%3}, {%4,%5,%6,%7}, {%8,%9}, {%0,%1,%2,%3};"
        : "+f"(d[0]), "+f"(d[1]), "+f"(d[2]), "+f"(d[3])
        : "r"(a0), "r"(a1), "r"(a2), "r"(a3), "r"(b0), "r"(b1));
}
__device__ __forceinline__ void mma_f16(float* d,
    uint32_t a0, uint32_t a1, uint32_t a2, uint32_t a3,
    uint32_t b0, uint32_t b1)
{
    asm volatile(
        "mma.sync.aligned.m16n8k16.row.col.f32.f16.f16.f32 "
        "{%0,%1,%2,%3}, {%4,%5,%6,%7}, {%8,%9}, {%0,%1,%2,%3};"
        : "+f"(d[0]), "+f"(d[1]), "+f"(d[2]), "+f"(d[3])
        : "r"(a0), "r"(a1), "r"(a2), "r"(a3), "r"(b0), "r"(b1));
}
__device__ __forceinline__ uint32_t pack_bf16_hi(float x, float y) {
    __nv_bfloat16 bx = __float2bfloat16(x), by = __float2bfloat16(y);
    return (uint32_t)__bfloat16_as_ushort(bx) | ((uint32_t)__bfloat16_as_ushort(by) << 16);
}
__device__ __forceinline__ uint32_t pack_bf16_lo(float x, float y) {
    __nv_bfloat16 bx = __float2bfloat16(x), by = __float2bfloat16(y);
    float rx = x - __bfloat162float(bx), ry = y - __bfloat162float(by);
    __nv_bfloat16 lx = __float2bfloat16(rx), ly = __float2bfloat16(ry);
    return (uint32_t)__bfloat16_as_ushort(lx) | ((uint32_t)__bfloat16_as_ushort(ly) << 16);
}
__device__ __forceinline__ uint32_t pack_f16(float x, float y) {
    __half hx = __float2half_rn(x), hy = __float2half_rn(y);
    return (uint32_t)__half_as_ushort(hx) | ((uint32_t)__half_as_ushort(hy) << 16);
}

// ---------------- software grid barrier (R1-proven) ----------------
__device__ __forceinline__ void grid_bar() {
    __syncthreads();
    if (threadIdx.x == 0) {
        unsigned gen = *(volatile unsigned*)&g_bar_phase;
        __threadfence();
        unsigned t = atomicAdd(&g_bar_arrive, 1u);
        if (t == NBLK - 1u) {
            *(volatile unsigned*)&g_bar_arrive = 0u;
            __threadfence();
            *(volatile unsigned*)&g_bar_phase = gen + 1u;
        } else {
            while (*(volatile unsigned*)&g_bar_phase == gen) {}
            __threadfence();
        }
    }
    __syncthreads();
}

// ---------------- init: misc + Whh f16 hi/lo B-frags + W_ih bf16 B-frags ----------------
__global__ void init_kernel(const float* __restrict__ Wih, const float* __restrict__ Whh) {
    int idx = blockIdx.x * blockDim.x + threadIdx.x;   // 0 .. 4194303
    if (idx < Bn) g_ptag[idx] = START_I;
    if (idx == 0) { g_loss = 0.0; g_bar_arrive = 0u; g_ptag_ready = 0u; }
    if (idx < Tn * G4n) {
        int t = idx >> 12;
        int n = idx & (G4n - 1);
        g_Wtag[idx] = Wih[(size_t)n * DTn + Hn + t];
    }
    if (idx < 2097152) {   // Whh f16 B-frags: which=0 -> f16 hi, which=1 -> f16 residual
        int lane  = idx & 31;
        int kt    = (idx >> 5) & 63;
        int nt    = (idx >> 11) & 3;
        int which = (idx >> 13) & 1;
        int bid   = idx >> 14;
        int g = lane >> 2, tig = lane & 3;
        int n = nt * 1024 + bid * 8 + g;
        int k0 = kt * 16 + 2 * tig;
        const float* W = Whh + (size_t)n * Hn;
        float v00 = W[k0], v01 = W[k0 + 1], v10 = W[k0 + 8], v11 = W[k0 + 9];
        uint32_t r0, r1;
        if (which == 0) {
            r0 = pack_f16(v00, v01);
            r1 = pack_f16(v10, v11);
        } else {
            float r00 = v00 - __half2float(__float2half_rn(v00));
            float r01 = v01 - __half2float(__float2half_rn(v01));
            float r10 = v10 - __half2float(__float2half_rn(v10));
            float r11 = v11 - __half2float(__float2half_rn(v11));
            r0 = pack_f16(r00, r01);
            r1 = pack_f16(r10, r11);
        }
        g_Bfrag[idx] = (u64t)r0 | ((u64t)r1 << 32);
    }
    if (idx < 1048576) {   // W_ih bf16 B-frags (xproj)
        int lane = idx & 31;
        int kt   = (idx >> 5) & 63;
        int nt2  = idx >> 11;
        int g = lane >> 2, tig = lane & 3;
        int n = nt2 * 8 + g;
        int k0 = kt * 16 + 2 * tig;
        const float* W = Wih + (size_t)n * DTn;
        float a = W[k0], b = W[k0 + 1], c = W[k0 + 8], d = W[k0 + 9];
        g_wfh[idx] = make_uint2(pack_bf16_hi(a, b), pack_bf16_hi(c, d));
        g_wfl[idx] = make_uint2(pack_bf16_lo(a, b), pack_bf16_lo(c, d));
    }
}

// ---------------- x -> A-fragment hi/lo bf16 (one-time) ----------------
__global__ void xprep_kernel(const float* __restrict__ x) {
    int idx = blockIdx.x * blockDim.x + threadIdx.x;
    int lane = idx & 31;
    int kt = (idx >> 5) & 63;
    int mt = idx >> 11;
    int g = lane >> 2, tig = lane & 3;
    int m0 = mt * 16 + g;
    int m1 = m0 + 8;
    int k0 = kt * 16 + 2 * tig;
    const float* r0 = x + ((size_t)((m0 & 127) * 256 + (m0 >> 7))) * Hn;
    const float* r1 = x + ((size_t)((m1 & 127) * 256 + (m1 >> 7))) * Hn;
    float2 v00 = *(const float2*)(r0 + k0);
    float2 v01 = *(const float2*)(r0 + k0 + 8);
    float2 v10 = *(const float2*)(r1 + k0);
    float2 v11 = *(const float2*)(r1 + k0 + 8);
    g_xh[idx] = make_uint4(pack_bf16_hi(v00.x, v00.y), pack_bf16_hi(v10.x, v10.y),
                           pack_bf16_hi(v01.x, v01.y), pack_bf16_hi(v11.x, v11.y));
    g_xl[idx] = make_uint4(pack_bf16_lo(v00.x, v00.y), pack_bf16_lo(v10.x, v10.y),
                           pack_bf16_lo(v01.x, v01.y), pack_bf16_lo(v11.x, v11.y));
}

// ---------------- phase 1: x-projection via HMMA bf16 3-split (R10, unchanged) ----------------
__global__ __launch_bounds__(256) void xproj_kernel(
    const float* __restrict__ bih, const float* __restrict__ bhh)
{
    const int tid = threadIdx.x;
    const int wid = tid >> 5, lane = tid & 31;
    const int g = lane >> 2, tig = lane & 3;
    const int wm = wid & 1, wn = wid >> 1;
    const int mt0 = blockIdx.y * 8 + wm * 4;
    const int nt0 = blockIdx.x * 16 + wn * 4;

    const uint4* Ah = g_xh + (size_t)mt0 * 2048 + lane;
    const uint4* Al = g_xl + (size_t)mt0 * 2048 + lane;
    const uint2* Bh = g_wfh + (size_t)nt0 * 2048 + lane;
    const uint2* Bl = g_wfl + (size_t)nt0 * 2048 + lane;

    float dacc[4][4][4];
#pragma unroll
    for (int i = 0; i < 4; i++)
#pragma unroll
        for (int j = 0; j < 4; j++)
#pragma unroll
            for (int e = 0; e < 4; e++) dacc[i][j][e] = 0.f;

    uint4 ah[4], al[4]; uint2 bh[4], bl[4];
#pragma unroll
    for (int i = 0; i < 4; i++) { ah[i] = __ldg(Ah + i * 2048); al[i] = __ldg(Al + i * 2048); }
#pragma unroll
    for (int j = 0; j < 4; j++) { bh[j] = __ldg(Bh + j * 2048); bl[j] = __ldg(Bl + j * 2048); }

    for (int kt = 0; kt < 64; kt++) {
        uint4 ahn[4], aln[4]; uint2 bhn[4], bln[4];
        if (kt < 63) {
#pragma unroll
            for (int i = 0; i < 4; i++) {
                ahn[i] = __ldg(Ah + i * 2048 + (kt + 1) * 32);
                aln[i] = __ldg(Al + i * 2048 + (kt + 1) * 32);
            }
#pragma unroll
            for (int j = 0; j < 4; j++) {
                bhn[j] = __ldg(Bh + j * 2048 + (kt + 1) * 32);
                bln[j] = __ldg(Bl + j * 2048 + (kt + 1) * 32);
            }
        }
#pragma unroll
        for (int i = 0; i < 4; i++)
#pragma unroll
            for (int j = 0; j < 4; j++)
                mma_bf16(dacc[i][j], ah[i].x, ah[i].y, ah[i].z, ah[i].w, bh[j].x, bh[j].y);
#pragma unroll
        for (int i = 0; i < 4; i++)
#pragma unroll
            for (int j = 0; j < 4; j++)
                mma_bf16(dacc[i][j], al[i].x, al[i].y, al[i].z, al[i].w, bh[j].x, bh[j].y);
#pragma unroll
        for (int i = 0; i < 4; i++)
#pragma unroll
            for (int j = 0; j < 4; j++)
                mma_bf16(dacc[i][j], ah[i].x, ah[i].y, ah[i].z, ah[i].w, bl[j].x, bl[j].y);
#pragma unroll
        for (int i = 0; i < 4; i++) { ah[i] = ahn[i]; al[i] = aln[i]; }
#pragma unroll
        for (int j = 0; j < 4; j++) { bh[j] = bhn[j]; bl[j] = bln[j]; }
    }

#pragma unroll
    for (int j = 0; j < 4; j++) {
        int n = (nt0 + j) * 8 + 2 * tig;
        float b0 = bih[n] + bhh[n];
        float b1 = bih[n + 1] + bhh[n + 1];
#pragma unroll
        for (int i = 0; i < 4; i++) {
            int m = (mt0 + i) * 16 + g;
            *(float2*)(g_G + (size_t)m * G4n + n) =
                make_float2(dacc[i][j][0] + b0, dacc[i][j][1] + b1);
            *(float2*)(g_G + (size_t)(m + 8) * G4n + n) =
                make_float2(dacc[i][j][2] + b0, dacc[i][j][3] + b1);
        }
    }
}

// ---------------- GEMM slice: fp16 A single-stream, W f16 hi+lo, 2 passes ----------------
template<int KCNT>
__device__ __forceinline__ void gemm_part(float (*dacc)[4],
    const uint4* __restrict__ Af4,
    const uint2* __restrict__ Bh, const uint2* __restrict__ Bl,
    int ktbase, int lane)
{
    uint4 afs[3];
#pragma unroll
    for (int d = 0; d < 3; d++) afs[d] = __ldcg(Af4 + d * 32);
#pragma unroll
    for (int ktl = 0; ktl < KCNT; ktl++) {
        const int sl = ktl % 3;
        uint4 af = afs[sl];
        if (ktl + 3 < KCNT) afs[sl] = __ldcg(Af4 + (ktl + 3) * 32);
        const int kt = ktbase + ktl;
        uint2 b0 = Bh[(0 * 64 + kt) * 32 + lane];
        uint2 b1r = Bh[(1 * 64 + kt) * 32 + lane];
        uint2 b2r = Bh[(2 * 64 + kt) * 32 + lane];
        uint2 b3 = Bh[(3 * 64 + kt) * 32 + lane];
        mma_f16(dacc[0], af.x, af.y, af.z, af.w, b0.x, b0.y);
        mma_f16(dacc[1], af.x, af.y, af.z, af.w, b1r.x, b1r.y);
        mma_f16(dacc[2], af.x, af.y, af.z, af.w, b2r.x, b2r.y);
        mma_f16(dacc[3], af.x, af.y, af.z, af.w, b3.x, b3.y);
        b0 = Bl[(0 * 64 + kt) * 32 + lane];
        b1r = Bl[(1 * 64 + kt) * 32 + lane];
        b2r = Bl[(2 * 64 + kt) * 32 + lane];
        b3 = Bl[(3 * 64 + kt) * 32 + lane];
        mma_f16(dacc[0], af.x, af.y, af.z, af.w, b0.x, b0.y);
        mma_f16(dacc[1], af.x, af.y, af.z, af.w, b1r.x, b1r.y);
        mma_f16(dacc[2], af.x, af.y, af.z, af.w, b2r.x, b2r.y);
        mma_f16(dacc[3], af.x, af.y, af.z, af.w, b3.x, b3.y);
    }
}

// ---------------- persistent loop: R10 structure, fp16-A GEMM ----------------
#define LOOP_SMEM 148480
#define KT0 44
#define KT1 20

__global__ __launch_bounds__(512, 1) void loop_kernel(
    const float* __restrict__ Wout, const float* __restrict__ bout,
    const int* __restrict__ tags, const int* __restrict__ mask,
    float* __restrict__ out)
{
    extern __shared__ __align__(16) unsigned char smem[];
    float* red = (float*)smem;
    const uint2* Bh = (const uint2*)(smem + 1024);
    const uint2* Bl = (const uint2*)(smem + 1024 + 65536);
    float* red2 = (float*)(smem + 132096);   // [16][256]

    const int bid = blockIdx.x;
    const int tid = threadIdx.x;
    const int wid = tid >> 5;
    const int lane = tid & 31;
    const int g = lane >> 2, tig = lane & 3;
    const int wk = wid >> 3;
    const int wm = wid & 7;
    const int gtid = tid & 255;

    {
        const uint4* src = (const uint4*)g_Bfrag + (size_t)bid * 8192;
        uint4* dst = (uint4*)(smem + 1024);
        for (int u = tid; u < 8192; u += 512) dst[u] = src[u];
    }
    __syncthreads();

    const int b1 = wm * 16 + g;
    const int b2 = b1 + 8;
    const int kkg0 = bid * 8 + 2 * tig;
    const int ktbase = wk ? KT0 : 0;

    float creg[2][2] = {{0.f, 0.f}, {0.f, 0.f}};
    double lossAcc = 0.0;

    // logits for step ls (h(ls) in g_h[(ls+1)&1]); wk1 threads only (R10-proven).
    auto do_logits = [&](int ls, bool feed) {
        const float4* h4 = (const float4*)(g_h[(ls + 1) & 1] + bid * Hn);
        float4 hvv = __ldcg(h4 + gtid);
        const float4* W4 = (const float4*)Wout;
        float p[Tn];
#pragma unroll
        for (int t = 0; t < Tn; t++) {
            float4 w = __ldg(W4 + t * 256 + gtid);
            p[t] = hvv.x * w.x + hvv.y * w.y + hvv.z * w.z + hvv.w * w.w;
        }
#pragma unroll
        for (int t = 0; t < Tn; t++) {
#pragma unroll
            for (int o = 16; o > 0; o >>= 1)
                p[t] += __shfl_xor_sync(0xffffffffu, p[t], o);
        }
        if (lane == 0) {
#pragma unroll
            for (int t = 0; t < Tn; t++) red[(gtid >> 5) * Tn + t] = p[t];
        }
        asm volatile("bar.sync 1, 256;" ::: "memory");
        if (gtid < 32) {
            float l = -3.402823466e38f;
            if (gtid < Tn) {
                l = bout[gtid];
#pragma unroll
                for (int w = 0; w < 8; w++) l += red[w * Tn + gtid];
            }
            float v = l; int idx = gtid;
#pragma unroll
            for (int o = 16; o > 0; o >>= 1) {
                float v2 = __shfl_xor_sync(0xffffffffu, v, o);
                int   i2 = __shfl_xor_sync(0xffffffffu, idx, o);
                if (v2 > v || (v2 == v && i2 < idx)) { v = v2; idx = i2; }
            }
            if (feed && gtid == 0) g_ptag[bid] = idx;
            if (mask[bid * Sn + ls] != 0) {
                float e = (gtid < Tn) ? expf(l - v) : 0.f;
#pragma unroll
                for (int o = 16; o > 0; o >>= 1)
                    e += __shfl_xor_sync(0xffffffffu, e, o);
                int y = tags[bid * Sn + ls];
                float ly = __shfl_sync(0xffffffffu, l, y);
                if (gtid == 0) lossAcc += (double)(v + logf(e) - ly);
            }
            if (feed && gtid == 0) {
                __threadfence();
                atomicAdd(&g_ptag_ready, 1u);
            }
        }
    };

    for (int s = 0; s < Sn; s++) {
        float2 Gv[2][4];
        if (tid < 256) {
#pragma unroll
            for (int r2 = 0; r2 < 2; r2++) {
                int r = r2 ? b2 : b1;
                const float* Gp = g_G + (size_t)(s * Bn + r) * G4n + kkg0;
#pragma unroll
                for (int nt = 0; nt < 4; nt++)
                    Gv[r2][nt] = __ldcs((const float2*)(Gp + nt * 1024));
            }
        }

        float dacc[4][4];
#pragma unroll
        for (int nt = 0; nt < 4; nt++)
#pragma unroll
            for (int e = 0; e < 4; e++) dacc[nt][e] = 0.f;

        if (s > 0) {
            if (wk == 1) do_logits(s - 1, true);   // overlaps wk0's GEMM

            const int par = s & 1;
            const uint4* Af4 = (const uint4*)g_hAf[par] + (wm * 2048 + ktbase * 32 + lane);
            if (wk == 0) gemm_part<KT0>(dacc, Af4, Bh, Bl, 0, lane);
            else         gemm_part<KT1>(dacc, Af4, Bh, Bl, KT0, lane);
        }

        // split-K: wk1 publishes, threads 0-255 accumulate
        if (wk == 1) {
#pragma unroll
            for (int nt = 0; nt < 4; nt++)
#pragma unroll
                for (int e = 0; e < 4; e++)
                    red2[(nt * 4 + e) * 256 + gtid] = dacc[nt][e];
        }
        __syncthreads();
        if (tid < 256) {
#pragma unroll
            for (int nt = 0; nt < 4; nt++)
#pragma unroll
                for (int e = 0; e < 4; e++)
                    dacc[nt][e] += red2[(nt * 4 + e) * 256 + tid];
        }

        if (s > 0) {
            if (tid == 0) {
                while (*(volatile unsigned*)&g_ptag_ready < (unsigned)s * 128u) {}
            }
            __syncthreads();
        }

        // ---- epilogue (threads 0-255) ----
        const int po = (s & 1) ^ 1;
        if (tid < 256) {
            int pt1 = __ldcg(&g_ptag[b1]);
            int pt2 = __ldcg(&g_ptag[b2]);
            const float* W1 = g_Wtag + pt1 * G4n + kkg0;
            const float* W2 = g_Wtag + pt2 * G4n + kkg0;
#pragma unroll
            for (int r2 = 0; r2 < 2; r2++) {
                int r = r2 ? b2 : b1;
                const float* Wt = r2 ? W2 : W1;
                float2 wt0 = *(const float2*)(Wt);
                float2 wt1 = *(const float2*)(Wt + 1024);
                float2 wt2 = *(const float2*)(Wt + 2048);
                float2 wt3 = *(const float2*)(Wt + 3072);
                float h01[2];
#pragma unroll
                for (int e = 0; e < 2; e++) {
                    int de = r2 * 2 + e;
                    float G0 = e ? Gv[r2][0].y : Gv[r2][0].x;
                    float G1 = e ? Gv[r2][1].y : Gv[r2][1].x;
                    float G2 = e ? Gv[r2][2].y : Gv[r2][2].x;
                    float G3 = e ? Gv[r2][3].y : Gv[r2][3].x;
                    float gi = dacc[0][de] + G0 + (e ? wt0.y : wt0.x);
                    float gf = dacc[1][de] + G1 + (e ? wt1.y : wt1.x);
                    float gg = dacc[2][de] + G2 + (e ? wt2.y : wt2.x);
                    float go = dacc[3][de] + G3 + (e ? wt3.y : wt3.x);
                    gi = 1.f / (1.f + __expf(-gi));
                    gf = 1.f / (1.f + __expf(-gf));
                    gg = tanhf(gg);
                    go = 1.f / (1.f + __expf(-go));
                    creg[r2][e] = gf * creg[r2][e] + gi * gg;
                    h01[e] = go * tanhf(creg[r2][e]);
                }
                *(float2*)(g_h[po] + r * Hn + kkg0) = make_float2(h01[0], h01[1]);
                int idx = ((r >> 4) * 8192) + ((bid >> 1) * 128)
                        + (((r & 7) * 4 + tig) * 4) + ((r >> 3) & 1) + 2 * (bid & 1);
                g_hAf[po][idx] = pack_f16(h01[0], h01[1]);
            }
        }
        grid_bar();
    }

    // tail: logits(255) (loss only)
    if (wk == 1) do_logits(Sn - 1, false);
    if (tid == 256) atomicAdd(&g_loss, lossAcc);
    grid_bar();
    if (bid == 0 && tid == 0) out[0] = (float)(*(volatile double*)&g_loss);
}

// ---------------- launch ----------------
extern "C" void kernel_launch(void* const* d_in, const int* in_sizes, int n_in,
                              void* d_out, int out_size)
{
    const float *x = nullptr, *Wih = nullptr, *Whh = nullptr;
    const float *bih = nullptr, *bhh = nullptr, *Wout = nullptr, *bout = nullptr;
    const int *tags = nullptr, *maskp = nullptr;
    for (int i = 0; i < n_in; i++) {
        int sz = in_sizes[i];
        const void* p = d_in[i];
        switch (sz) {
            case 33554432: x = (const float*)p; break;
            case 4276224:  Wih = (const float*)p; break;
            case 4194304:  Whh = (const float*)p; break;
            case 4096:     if (!bih) bih = (const float*)p; else bhh = (const float*)p; break;
            case 32768:    if (!tags) tags = (const int*)p; else maskp = (const int*)p; break;
            case 20480:    Wout = (const float*)p; break;
            case 20:       bout = (const float*)p; break;
            default: break;
        }
    }

    cudaFuncSetAttribute(loop_kernel, cudaFuncAttributeMaxDynamicSharedMemorySize, LOOP_SMEM);

    init_kernel<<<16384, 256>>>(Wih, Whh);                               // #1
    xprep_kernel<<<16384, 256>>>(x);                                     // #2
    xproj_kernel<<<dim3(32, 256), 256>>>(bih, bhh);                      // #3
    loop_kernel<<<NBLK, 512, LOOP_SMEM>>>(Wout, bout, tags, maskp, (float*)d_out);  // #4 (profiled)
}

// round 16
// speedup vs baseline: 3.1161x; 1.6352x over previous
#include <cuda_runtime.h>
#include <cuda_fp16.h>
#include <cstdint>

#define Bn 128
#define Sn 256
#define Hn 1024
#define Tn 20
#define G4n 4096
#define DTn 1044
#define START_I 19
#define NBLK 128u

typedef unsigned long long u64t;

// ---------------- device scratch ----------------
__device__ float g_G[(size_t)Sn * Bn * G4n];                 // x-projection + biases (fp32)
__device__ float g_h[2][Bn * Hn];                            // fp32 h (for logits)
__device__ float g_Wtag[Tn * G4n];                           // one-hot columns of W_ih
__device__ __align__(16) u64t g_Bf[1048576];                 // Whh f16 B-frags (8MB)
__device__ __align__(16) uint32_t g_hAf[2][65536];           // h fp16 A-frags (ping-pong)
__device__ __align__(16) uint4 g_xf[4194304];                // x f16 A-frags (67MB, xproj)
__device__ __align__(16) uint2 g_wf[1048576];                // W_ih f16 B-frags (8MB)
__device__ int   g_ptag[Bn];
__device__ double g_loss;
__device__ unsigned g_bar_arrive, g_bar_phase, g_ptag_ready;

// ---------------- mma wrappers ----------------
__device__ __forceinline__ void mma_f16(float* d,
    uint32_t a0, uint32_t a1, uint32_t a2, uint32_t a3,
    uint32_t b0, uint32_t b1)
{
    asm volatile(
        "mma.sync.aligned.m16n8k16.row.col.f32.f16.f16.f32 "
        "{%0,%1,%2,%3}, {%4,%5,%6,%7}, {%8,%9}, {%0,%1,%2,%3};"
        : "+f"(d[0]), "+f"(d[1]), "+f"(d[2]), "+f"(d[3])
        : "r"(a0), "r"(a1), "r"(a2), "r"(a3), "r"(b0), "r"(b1));
}
__device__ __forceinline__ uint32_t pack_f16(float x, float y) {
    __half hx = __float2half_rn(x), hy = __float2half_rn(y);
    return (uint32_t)__half_as_ushort(hx) | ((uint32_t)__half_as_ushort(hy) << 16);
}

// ---------------- software grid barrier (R1-proven) ----------------
__device__ __forceinline__ void grid_bar() {
    __syncthreads();
    if (threadIdx.x == 0) {
        unsigned gen = *(volatile unsigned*)&g_bar_phase;
        __threadfence();
        unsigned t = atomicAdd(&g_bar_arrive, 1u);
        if (t == NBLK - 1u) {
            *(volatile unsigned*)&g_bar_arrive = 0u;
            __threadfence();
            *(volatile unsigned*)&g_bar_phase = gen + 1u;
        } else {
            while (*(volatile unsigned*)&g_bar_phase == gen) {}
            __threadfence();
        }
    }
    __syncthreads();
}

// ---------------- init: misc + Whh f16 B-frags + W_ih f16 B-frags ----------------
__global__ void init_kernel(const float* __restrict__ Wih, const float* __restrict__ Whh) {
    int idx = blockIdx.x * blockDim.x + threadIdx.x;   // 0 .. 4194303
    if (idx < Bn) g_ptag[idx] = START_I;
    if (idx == 0) { g_loss = 0.0; g_bar_arrive = 0u; g_ptag_ready = 0u; }
    if (idx < Tn * G4n) {
        int t = idx >> 12;
        int n = idx & (G4n - 1);
        g_Wtag[idx] = Wih[(size_t)n * DTn + Hn + t];
    }
    if (idx < 1048576) {   // Whh f16 B-frags: ((bid*4+nt)*64+kt)*32+lane
        int lane = idx & 31;
        int kt   = (idx >> 5) & 63;
        int nt   = (idx >> 11) & 3;
        int bid  = idx >> 13;
        int g = lane >> 2, tig = lane & 3;
        int n = nt * 1024 + bid * 8 + g;
        int k0 = kt * 16 + 2 * tig;
        const float* W = Whh + (size_t)n * Hn;
        uint32_t r0 = pack_f16(W[k0], W[k0 + 1]);
        uint32_t r1 = pack_f16(W[k0 + 8], W[k0 + 9]);
        g_Bf[idx] = (u64t)r0 | ((u64t)r1 << 32);
    }
    if (idx < 1048576) {   // W_ih f16 B-frags (xproj)
        int lane = idx & 31;
        int kt   = (idx >> 5) & 63;
        int nt2  = idx >> 11;
        int g = lane >> 2, tig = lane & 3;
        int n = nt2 * 8 + g;
        int k0 = kt * 16 + 2 * tig;
        const float* W = Wih + (size_t)n * DTn;
        g_wf[idx] = make_uint2(pack_f16(W[k0], W[k0 + 1]), pack_f16(W[k0 + 8], W[k0 + 9]));
    }
}

// ---------------- x -> f16 A-frags (one-time) ----------------
__global__ void xprep_kernel(const float* __restrict__ x) {
    int idx = blockIdx.x * blockDim.x + threadIdx.x;
    int lane = idx & 31;
    int kt = (idx >> 5) & 63;
    int mt = idx >> 11;
    int g = lane >> 2, tig = lane & 3;
    int m0 = mt * 16 + g;
    int m1 = m0 + 8;
    int k0 = kt * 16 + 2 * tig;
    const float* r0 = x + ((size_t)((m0 & 127) * 256 + (m0 >> 7))) * Hn;
    const float* r1 = x + ((size_t)((m1 & 127) * 256 + (m1 >> 7))) * Hn;
    float2 v00 = *(const float2*)(r0 + k0);
    float2 v01 = *(const float2*)(r0 + k0 + 8);
    float2 v10 = *(const float2*)(r1 + k0);
    float2 v11 = *(const float2*)(r1 + k0 + 8);
    g_xf[idx] = make_uint4(pack_f16(v00.x, v00.y), pack_f16(v10.x, v10.y),
                           pack_f16(v01.x, v01.y), pack_f16(v11.x, v11.y));
}

// ---------------- phase 1: x-projection via single-pass f16 HMMA ----------------
__global__ __launch_bounds__(256) void xproj_kernel(
    const float* __restrict__ bih, const float* __restrict__ bhh)
{
    const int tid = threadIdx.x;
    const int wid = tid >> 5, lane = tid & 31;
    const int g = lane >> 2, tig = lane & 3;
    const int wm = wid & 1, wn = wid >> 1;
    const int mt0 = blockIdx.y * 8 + wm * 4;
    const int nt0 = blockIdx.x * 16 + wn * 4;

    const uint4* Af = g_xf + (size_t)mt0 * 2048 + lane;
    const uint2* Bf = g_wf + (size_t)nt0 * 2048 + lane;

    float dacc[4][4][4];
#pragma unroll
    for (int i = 0; i < 4; i++)
#pragma unroll
        for (int j = 0; j < 4; j++)
#pragma unroll
            for (int e = 0; e < 4; e++) dacc[i][j][e] = 0.f;

    uint4 a[4]; uint2 b[4];
#pragma unroll
    for (int i = 0; i < 4; i++) a[i] = __ldg(Af + i * 2048);
#pragma unroll
    for (int j = 0; j < 4; j++) b[j] = __ldg(Bf + j * 2048);

    for (int kt = 0; kt < 64; kt++) {
        uint4 an[4]; uint2 bn[4];
        if (kt < 63) {
#pragma unroll
            for (int i = 0; i < 4; i++) an[i] = __ldg(Af + i * 2048 + (kt + 1) * 32);
#pragma unroll
            for (int j = 0; j < 4; j++) bn[j] = __ldg(Bf + j * 2048 + (kt + 1) * 32);
        }
#pragma unroll
        for (int i = 0; i < 4; i++)
#pragma unroll
            for (int j = 0; j < 4; j++)
                mma_f16(dacc[i][j], a[i].x, a[i].y, a[i].z, a[i].w, b[j].x, b[j].y);
#pragma unroll
        for (int i = 0; i < 4; i++) a[i] = an[i];
#pragma unroll
        for (int j = 0; j < 4; j++) b[j] = bn[j];
    }

#pragma unroll
    for (int j = 0; j < 4; j++) {
        int n = (nt0 + j) * 8 + 2 * tig;
        float b0 = bih[n] + bhh[n];
        float b1 = bih[n + 1] + bhh[n + 1];
#pragma unroll
        for (int i = 0; i < 4; i++) {
            int m = (mt0 + i) * 16 + g;
            *(float2*)(g_G + (size_t)m * G4n + n) =
                make_float2(dacc[i][j][0] + b0, dacc[i][j][1] + b1);
            *(float2*)(g_G + (size_t)(m + 8) * G4n + n) =
                make_float2(dacc[i][j][2] + b0, dacc[i][j][3] + b1);
        }
    }
}

// ---------------- persistent loop: wk0 = full-K f16 GEMM + epilogue, wk1 = logits ----------------
// smem: [0..1024) red, [1024..66560) Bf frags
#define LOOP_SMEM 66560

__global__ __launch_bounds__(512, 1) void loop_kernel(
    const float* __restrict__ Wout, const float* __restrict__ bout,
    const int* __restrict__ tags, const int* __restrict__ mask,
    float* __restrict__ out)
{
    extern __shared__ __align__(16) unsigned char smem[];
    float* red = (float*)smem;
    const uint2* Bh = (const uint2*)(smem + 1024);

    const int bid = blockIdx.x;
    const int tid = threadIdx.x;
    const int wid = tid >> 5;
    const int lane = tid & 31;
    const int g = lane >> 2, tig = lane & 3;
    const int wk = wid >> 3;
    const int wm = wid & 7;
    const int gtid = tid & 255;

    {
        const uint4* src = (const uint4*)g_Bf + (size_t)bid * 4096;
        uint4* dst = (uint4*)(smem + 1024);
        for (int u = tid; u < 4096; u += 512) dst[u] = src[u];
    }
    __syncthreads();

    const int b1 = wm * 16 + g;
    const int b2 = b1 + 8;
    const int kkg0 = bid * 8 + 2 * tig;

    float creg[2][2] = {{0.f, 0.f}, {0.f, 0.f}};
    double lossAcc = 0.0;

    // logits for step ls (h(ls) in g_h[(ls+1)&1]); wk1 threads only.
    auto do_logits = [&](int ls, bool feed) {
        const float4* h4 = (const float4*)(g_h[(ls + 1) & 1] + bid * Hn);
        float4 hvv = __ldcg(h4 + gtid);
        const float4* W4 = (const float4*)Wout;
        float p[Tn];
#pragma unroll
        for (int t = 0; t < Tn; t++) {
            float4 w = __ldg(W4 + t * 256 + gtid);
            p[t] = hvv.x * w.x + hvv.y * w.y + hvv.z * w.z + hvv.w * w.w;
        }
#pragma unroll
        for (int t = 0; t < Tn; t++) {
#pragma unroll
            for (int o = 16; o > 0; o >>= 1)
                p[t] += __shfl_xor_sync(0xffffffffu, p[t], o);
        }
        if (lane == 0) {
#pragma unroll
            for (int t = 0; t < Tn; t++) red[(gtid >> 5) * Tn + t] = p[t];
        }
        asm volatile("bar.sync 1, 256;" ::: "memory");
        if (gtid < 32) {
            float l = -3.402823466e38f;
            if (gtid < Tn) {
                l = bout[gtid];
#pragma unroll
                for (int w = 0; w < 8; w++) l += red[w * Tn + gtid];
            }
            float v = l; int idx = gtid;
#pragma unroll
            for (int o = 16; o > 0; o >>= 1) {
                float v2 = __shfl_xor_sync(0xffffffffu, v, o);
                int   i2 = __shfl_xor_sync(0xffffffffu, idx, o);
                if (v2 > v || (v2 == v && i2 < idx)) { v = v2; idx = i2; }
            }
            if (feed && gtid == 0) g_ptag[bid] = idx;
            if (mask[bid * Sn + ls] != 0) {
                float e = (gtid < Tn) ? expf(l - v) : 0.f;
#pragma unroll
                for (int o = 16; o > 0; o >>= 1)
                    e += __shfl_xor_sync(0xffffffffu, e, o);
                int y = tags[bid * Sn + ls];
                float ly = __shfl_sync(0xffffffffu, l, y);
                if (gtid == 0) lossAcc += (double)(v + logf(e) - ly);
            }
            if (feed && gtid == 0) {
                __threadfence();
                atomicAdd(&g_ptag_ready, 1u);
            }
        }
    };

    for (int s = 0; s < Sn; s++) {
        float2 Gv[2][4];
        if (tid < 256) {
#pragma unroll
            for (int r2 = 0; r2 < 2; r2++) {
                int r = r2 ? b2 : b1;
                const float* Gp = g_G + (size_t)(s * Bn + r) * G4n + kkg0;
#pragma unroll
                for (int nt = 0; nt < 4; nt++)
                    Gv[r2][nt] = __ldcs((const float2*)(Gp + nt * 1024));
            }
        }

        float dacc[4][4];
#pragma unroll
        for (int nt = 0; nt < 4; nt++)
#pragma unroll
            for (int e = 0; e < 4; e++) dacc[nt][e] = 0.f;

        if (s > 0) {
            if (wk == 1) {
                do_logits(s - 1, true);   // overlaps wk0's GEMM
            } else {
                // wk0: full-K single-pass f16 GEMM
                const int par = s & 1;
                const uint4* Af4 = (const uint4*)g_hAf[par] + (wm * 2048 + lane);
                uint4 afs[3];
#pragma unroll
                for (int d = 0; d < 3; d++) afs[d] = __ldcg(Af4 + d * 32);
#pragma unroll
                for (int kt = 0; kt < 64; kt++) {
                    const int sl = kt % 3;
                    uint4 af = afs[sl];
                    if (kt + 3 < 64) afs[sl] = __ldcg(Af4 + (kt + 3) * 32);
                    uint2 b0 = Bh[(0 * 64 + kt) * 32 + lane];
                    uint2 b1r = Bh[(1 * 64 + kt) * 32 + lane];
                    uint2 b2r = Bh[(2 * 64 + kt) * 32 + lane];
                    uint2 b3 = Bh[(3 * 64 + kt) * 32 + lane];
                    mma_f16(dacc[0], af.x, af.y, af.z, af.w, b0.x, b0.y);
                    mma_f16(dacc[1], af.x, af.y, af.z, af.w, b1r.x, b1r.y);
                    mma_f16(dacc[2], af.x, af.y, af.z, af.w, b2r.x, b2r.y);
                    mma_f16(dacc[3], af.x, af.y, af.z, af.w, b3.x, b3.y);
                }
            }
        }

        // ptag wait (all 512 threads sync; wk1 finished logits above)
        if (s > 0) {
            if (tid == 0) {
                while (*(volatile unsigned*)&g_ptag_ready < (unsigned)s * 128u) {}
            }
            __syncthreads();
        }

        // ---- epilogue (threads 0-255 = wk0, who own dacc) ----
        const int po = (s & 1) ^ 1;
        if (tid < 256) {
            int pt1 = __ldcg(&g_ptag[b1]);
            int pt2 = __ldcg(&g_ptag[b2]);
            const float* W1 = g_Wtag + pt1 * G4n + kkg0;
            const float* W2 = g_Wtag + pt2 * G4n + kkg0;
#pragma unroll
            for (int r2 = 0; r2 < 2; r2++) {
                int r = r2 ? b2 : b1;
                const float* Wt = r2 ? W2 : W1;
                float2 wt0 = *(const float2*)(Wt);
                float2 wt1 = *(const float2*)(Wt + 1024);
                float2 wt2 = *(const float2*)(Wt + 2048);
                float2 wt3 = *(const float2*)(Wt + 3072);
                float h01[2];
#pragma unroll
                for (int e = 0; e < 2; e++) {
                    int de = r2 * 2 + e;
                    float G0 = e ? Gv[r2][0].y : Gv[r2][0].x;
                    float G1 = e ? Gv[r2][1].y : Gv[r2][1].x;
                    float G2 = e ? Gv[r2][2].y : Gv[r2][2].x;
                    float G3 = e ? Gv[r2][3].y : Gv[r2][3].x;
                    float gi = dacc[0][de] + G0 + (e ? wt0.y : wt0.x);
                    float gf = dacc[1][de] + G1 + (e ? wt1.y : wt1.x);
                    float gg = dacc[2][de] + G2 + (e ? wt2.y : wt2.x);
                    float go = dacc[3][de] + G3 + (e ? wt3.y : wt3.x);
                    gi = 1.f / (1.f + __expf(-gi));
                    gf = 1.f / (1.f + __expf(-gf));
                    gg = tanhf(gg);
                    go = 1.f / (1.f + __expf(-go));
                    creg[r2][e] = gf * creg[r2][e] + gi * gg;
                    h01[e] = go * tanhf(creg[r2][e]);
                }
                *(float2*)(g_h[po] + r * Hn + kkg0) = make_float2(h01[0], h01[1]);
                int idx = ((r >> 4) * 8192) + ((bid >> 1) * 128)
                        + (((r & 7) * 4 + tig) * 4) + ((r >> 3) & 1) + 2 * (bid & 1);
                g_hAf[po][idx] = pack_f16(h01[0], h01[1]);
            }
        }
        grid_bar();
    }

    // tail: logits(255) (loss only)
    if (wk == 1) do_logits(Sn - 1, false);
    if (tid == 256) atomicAdd(&g_loss, lossAcc);
    grid_bar();
    if (bid == 0 && tid == 0) out[0] = (float)(*(volatile double*)&g_loss);
}

// ---------------- launch ----------------
extern "C" void kernel_launch(void* const* d_in, const int* in_sizes, int n_in,
                              void* d_out, int out_size)
{
    const float *x = nullptr, *Wih = nullptr, *Whh = nullptr;
    const float *bih = nullptr, *bhh = nullptr, *Wout = nullptr, *bout = nullptr;
    const int *tags = nullptr, *maskp = nullptr;
    for (int i = 0; i < n_in; i++) {
        int sz = in_sizes[i];
        const void* p = d_in[i];
        switch (sz) {
            case 33554432: x = (const float*)p; break;
            case 4276224:  Wih = (const float*)p; break;
            case 4194304:  Whh = (const float*)p; break;
            case 4096:     if (!bih) bih = (const float*)p; else bhh = (const float*)p; break;
            case 32768:    if (!tags) tags = (const int*)p; else maskp = (const int*)p; break;
            case 20480:    Wout = (const float*)p; break;
            case 20:       bout = (const float*)p; break;
            default: break;
        }
    }

    cudaFuncSetAttribute(loop_kernel, cudaFuncAttributeMaxDynamicSharedMemorySize, LOOP_SMEM);

    init_kernel<<<16384, 256>>>(Wih, Whh);                               // #1
    xprep_kernel<<<16384, 256>>>(x);                                     // #2
    xproj_kernel<<<dim3(32, 256), 256>>>(bih, bhh);                      // #3
    loop_kernel<<<NBLK, 512, LOOP_SMEM>>>(Wout, bout, tags, maskp, (float*)d_out);  // #4 (profiled)
}